// round 8
// baseline (speedup 1.0000x reference)
#include <cuda_runtime.h>
#include <stdint.h>
#include <math.h>

#define NSEQ 256
#define TLEN 32
#define MROWS 8192      // NSEQ*TLEN
#define ENCD 200

// scratch (static device allocations are allowed)
__device__ float g_P  [MROWS * 800];
__device__ float g_Ya [MROWS * ENCD];
__device__ float g_Yb [MROWS * ENCD];
__device__ float g_enc[NSEQ * ENCD];
__device__ float g_stk[NSEQ * ENCD];

__device__ __forceinline__ float sigf(float x) { return 1.0f / (1.0f + expf(-x)); }
// accurate tanh via expf (robust even under fast-math)
__device__ __forceinline__ float tanh_acc(float x) {
    float e = expf(-2.0f * fabsf(x));
    float r = (1.0f - e) / (1.0f + e);
    return x >= 0.0f ? r : -r;
}
__device__ __forceinline__ float4 ldcg4(const float* p) {
    float4 v;
    asm volatile("ld.global.cg.v4.f32 {%0,%1,%2,%3}, [%4];"
                 : "=f"(v.x), "=f"(v.y), "=f"(v.z), "=f"(v.w) : "l"(p));
    return v;
}
__device__ __forceinline__ void stcg(float* p, float v) {
    asm volatile("st.global.cg.f32 [%0], %1;" :: "l"(p), "f"(v));
}
__device__ __forceinline__ void stcg2(float* p, float2 v) {
    asm volatile("st.global.cg.v2.f32 [%0], {%1,%2};"
                 :: "l"(p), "f"(v.x), "f"(v.y));
}
__device__ __forceinline__ unsigned int smem_u32(const void* p) {
    unsigned int a;
    asm("{ .reg .u64 t; cvta.to.shared.u64 t, %1; cvt.u32.u64 %0, t; }"
        : "=r"(a) : "l"(p));
    return a;
}
__device__ __forceinline__ unsigned int ctarank() {
    unsigned int r; asm("mov.u32 %0, %%cluster_ctarank;" : "=r"(r)); return r;
}
__device__ __forceinline__ void st_remote_f32(unsigned int laddr, unsigned int rk, float v) {
    asm volatile(
        "{ .reg .b32 ra; mapa.shared::cluster.u32 ra, %0, %1; "
        "st.shared::cluster.f32 [ra], %2; }"
        :: "r"(laddr), "r"(rk), "f"(v) : "memory");
}
__device__ __forceinline__ void mbar_init(unsigned int addr, unsigned int count) {
    asm volatile("mbarrier.init.shared.b64 [%0], %1;" :: "r"(addr), "r"(count) : "memory");
}
// arrive with EXPLICIT release.cluster (orders prior DSMEM/global stores)
__device__ __forceinline__ void mbar_arrive_rank(unsigned int laddr, unsigned int rk) {
    asm volatile(
        "{ .reg .b32 ra; mapa.shared::cluster.u32 ra, %0, %1; "
        "mbarrier.arrive.release.cluster.shared::cluster.b64 _, [ra]; }"
        :: "r"(laddr), "r"(rk) : "memory");
}
// CTA-scope acquire wait: all cross-CTA data paths (DSMEM->own smem,
// .cg<->.cg via L2) bypass L1, so no cluster-scope (L1-invalidating) acquire.
__device__ __forceinline__ void mbar_wait_cta(unsigned int addr, unsigned int parity) {
    asm volatile(
        "{\n\t.reg .pred P1;\n\t"
        "WL%=:\n\t"
        "mbarrier.try_wait.parity.acquire.cta.shared::cta.b64 P1, [%0], %1, 0x989680;\n\t"
        "@P1 bra.uni WD%=;\n\t"
        "bra.uni WL%=;\n\t"
        "WD%=:\n\t}"
        :: "r"(addr), "r"(parity) : "memory");
}

// ---------------------------------------------------------------------------
// P[m][800] = A[row(m)][0:K] @ W[n][0:K]^T + bias[n]
// ---------------------------------------------------------------------------
__global__ __launch_bounds__(256) void proj_gemm(
    const float* __restrict__ Asrc, const int* __restrict__ tok,
    const float* __restrict__ W, const float* __restrict__ bias,
    float* __restrict__ P, int K)
{
    __shared__ float As[20 * 68];
    __shared__ float Ws[20 * 80];
    __shared__ unsigned long long roff[64];

    const int tid = threadIdx.x;
    const int M0 = blockIdx.x * 64;
    const int N0 = blockIdx.y * 80;

    if (tid < 64) {
        long long o = tok ? (long long)__ldg(&tok[M0 + tid]) * (long long)K
                          : (long long)(M0 + tid) * (long long)K;
        roff[tid] = (unsigned long long)o;
    }
    const int m0 = (tid >> 4) * 4;
    const int n0 = (tid & 15) * 5;

    float acc[4][5];
#pragma unroll
    for (int i = 0; i < 4; i++)
#pragma unroll
        for (int j = 0; j < 5; j++) acc[i][j] = 0.0f;
    __syncthreads();

    for (int kt = 0; kt < K; kt += 20) {
        {
            int i0 = tid * 5;
            int mm = i0 / 20, kk = i0 % 20;
            const float* ap = Asrc + roff[mm] + kt + kk;
#pragma unroll
            for (int q = 0; q < 5; q++) As[(kk + q) * 68 + mm] = ap[q];
        }
        for (int i = tid; i < 1600; i += 256) {
            int nn = i / 20, kk = i % 20;
            Ws[kk * 80 + nn] = __ldg(&W[(size_t)(N0 + nn) * K + kt + kk]);
        }
        __syncthreads();
#pragma unroll
        for (int kk = 0; kk < 20; kk++) {
            float4 a4 = *(const float4*)&As[kk * 68 + m0];
            float a[4] = {a4.x, a4.y, a4.z, a4.w};
            float b[5];
#pragma unroll
            for (int j = 0; j < 5; j++) b[j] = Ws[kk * 80 + n0 + j];
#pragma unroll
            for (int i = 0; i < 4; i++)
#pragma unroll
                for (int j = 0; j < 5; j++) acc[i][j] += a[i] * b[j];
        }
        __syncthreads();
    }
#pragma unroll
    for (int i = 0; i < 4; i++) {
        size_t row = (size_t)(M0 + m0 + i) * 800 + N0 + n0;
#pragma unroll
        for (int j = 0; j < 5; j++)
            P[row + j] = acc[i][j] + __ldg(&bias[N0 + n0 + j]);
    }
}

// ---------------------------------------------------------------------------
// LSTM recurrence (400 threads, pipelined P loads). If encOut != null
// (final layer), skip Y writes and emit mean-pooled enc directly.
// ---------------------------------------------------------------------------
__global__ __launch_bounds__(400, 1) void lstm_rec(
    const float* __restrict__ P, const float* __restrict__ Whh2,
    const int* __restrict__ lengths, float* __restrict__ Y,
    float* __restrict__ encOut)
{
    extern __shared__ float sm[];
    float* sW = sm;
    float* sH = sm + 40000;
    float* sC = sH + 400;
    float* sG = sC + 400;

    const int tid = threadIdx.x;
    const int dir = blockIdx.y;
    const int sq0 = blockIdx.x * 4;

    const float* Wd = Whh2 + dir * 40000;
    for (int i = tid; i < 40000; i += 400) sW[i] = Wd[i];
    for (int i = tid; i < 800; i += 400) sm[40000 + i] = 0.0f;

    const int sPW = tid / 100;
    const int jPW = tid % 100;
    const int myLen = __ldg(&lengths[sq0 + sPW]);
    __syncthreads();

    const float4* sW4 = (const float4*)(sW + tid * 100);
    const float4* sH4 = (const float4*)sH;

    float p0, p1, p2, p3;
    {
        int t = dir ? (TLEN - 1) : 0;
        size_t base = ((size_t)sq0 * TLEN + t) * 800 + dir * 400 + tid;
        p0 = __ldg(&P[base]);
        p1 = __ldg(&P[base + 1 * TLEN * 800]);
        p2 = __ldg(&P[base + 2 * TLEN * 800]);
        p3 = __ldg(&P[base + 3 * TLEN * 800]);
    }
    float hsum = 0.0f;

    for (int st = 0; st < TLEN; st++) {
        int t = dir ? (TLEN - 1 - st) : st;
        float acc0 = p0, acc1 = p1, acc2 = p2, acc3 = p3;
        if (st + 1 < TLEN) {
            int tn = dir ? (TLEN - 2 - st) : (st + 1);
            size_t base = ((size_t)sq0 * TLEN + tn) * 800 + dir * 400 + tid;
            p0 = __ldg(&P[base]);
            p1 = __ldg(&P[base + 1 * TLEN * 800]);
            p2 = __ldg(&P[base + 2 * TLEN * 800]);
            p3 = __ldg(&P[base + 3 * TLEN * 800]);
        }
#pragma unroll
        for (int kq = 0; kq < 25; kq++) {
            float4 w = sW4[kq];
            float4 h0 = sH4[kq], h1 = sH4[25 + kq], h2 = sH4[50 + kq], h3 = sH4[75 + kq];
            acc0 += w.x * h0.x + w.y * h0.y + w.z * h0.z + w.w * h0.w;
            acc1 += w.x * h1.x + w.y * h1.y + w.z * h1.z + w.w * h1.w;
            acc2 += w.x * h2.x + w.y * h2.y + w.z * h2.z + w.w * h2.w;
            acc3 += w.x * h3.x + w.y * h3.y + w.z * h3.z + w.w * h3.w;
        }
        sG[tid] = acc0; sG[400 + tid] = acc1; sG[800 + tid] = acc2; sG[1200 + tid] = acc3;
        __syncthreads();
        {
            float gi = sG[sPW * 400 + jPW];
            float gf = sG[sPW * 400 + 100 + jPW];
            float gg = sG[sPW * 400 + 200 + jPW];
            float go = sG[sPW * 400 + 300 + jPW];
            float c  = sC[sPW * 100 + jPW];
            float cn = sigf(gf) * c + sigf(gi) * tanh_acc(gg);
            float hn = sigf(go) * tanh_acc(cn);
            float outv = 0.0f;
            if (t < myLen) {
                sC[sPW * 100 + jPW] = cn;
                sH[sPW * 100 + jPW] = hn;
                outv = hn;
            }
            if (encOut) hsum += outv;
            else Y[((size_t)(sq0 + sPW) * TLEN + t) * ENCD + dir * 100 + jPW] = outv;
        }
        __syncthreads();
    }
    if (encOut)
        encOut[(sq0 + sPW) * ENCD + dir * 100 + jPW] = hsum / (float)myLen;
}

// ---------------------------------------------------------------------------
// Parser: 4-CTA cluster, unit-partitioned Wt (125 rows / 100 KB per CTA).
// 384 threads: warps 0-7 speculative gate GEMV, warps 8-9 one score row each,
// warps 10-11 prefetch. Commit on warp 0 only (+__syncwarp), arrives tid<4,
// cta-scope acquire wait. No fences, no full barrier after commit.
// ---------------------------------------------------------------------------
#define PRS_WT    0
#define PRS_WA    25000
#define PRS_BT    26200
#define PRS_BUF   26328
#define PRS_G     27528
#define PRS_MISS  27656
#define PRS_SC    27856
#define PRS_MBAR  27860
#define PRS_TOTAL 27864
#define PR_THREADS 384
#define PCLUSTER 4

__global__ __cluster_dims__(PCLUSTER, 1, 1) __launch_bounds__(PR_THREADS, 1) void parser4(
    const float* __restrict__ missing, const float* __restrict__ Wa,
    const float* __restrict__ ba, const float* __restrict__ Wt,
    const float* __restrict__ bt, float* __restrict__ out)
{
    extern __shared__ float sm[];
    float* sWt   = sm + PRS_WT;    // 125 rows x 200
    float* sWa   = sm + PRS_WA;    // 1200
    float* sBt   = sm + PRS_BT;    // 125
    float* sBuf  = sm + PRS_BUF;   // 6 x 200
    float* sG    = sm + PRS_G;     // 125
    float* sMiss = sm + PRS_MISS;  // 200
    float* sSc   = sm + PRS_SC;    // 2
    const int tid = threadIdx.x;
    const unsigned int rank = ctarank();
    const unsigned int mbarA = smem_u32(sm + PRS_MBAR);
    const unsigned int sBufA = smem_u32(sBuf);

    // own Wt rows: local row r (0..124): gate g=r/25, unit u=r%25
    for (int i = tid; i < 125 * 200; i += PR_THREADS) {
        int r = i / 200, k = i - r * 200;
        int grow = (r / 25) * 100 + (int)rank * 25 + (r % 25);
        sWt[i] = __ldg(&Wt[grow * 200 + k]);
    }
    for (int i = tid; i < 1200; i += PR_THREADS) sWa[i] = __ldg(&Wa[i]);
    if (tid < 125) {
        int grow = (tid / 25) * 100 + (int)rank * 25 + (tid % 25);
        sBt[tid] = __ldg(&bt[grow]);
    }
    if (tid < 200) {
        float mv = __ldg(&missing[tid]);
        sMiss[tid] = mv;
        sBuf[0 * 200 + tid] = mv;                    // i1 = missing
        sBuf[1 * 200 + tid] = mv;                    // i0 = missing
        sBuf[2 * 200 + tid] = __ldg(&g_enc[tid]);    // ib = enc[0]
    }
    const float ba0 = __ldg(&ba[0]), ba1 = __ldg(&ba[1]);
    if (tid == 0) mbar_init(mbarA, PCLUSTER);
    __syncthreads();
    asm volatile("barrier.cluster.arrive.aligned;" ::: "memory");
    asm volatile("barrier.cluster.wait.aligned;"   ::: "memory");

    int i1 = 0, i0 = 1, ib = 2, ipre = 3, ibn = 4, isp = 5;
    int sp = 0, bp = 0;
    const int warp = tid >> 5;
    const int lane = tid & 31;

    for (int step = 0; step < 2 * NSEQ - 1; step++) {
        // ==== PHASE A: all independent work in parallel ====
        // warps 0-7: SPECULATIVE TreeLSTM gate GEMV over own 125 rows
        if (tid < 250) {
            int r = tid >> 1, ph = tid & 1;
            const float4* wp4 = (const float4*)(sWt + r * 200 + ph * 100);
            const float4* xp  = (const float4*)(sBuf + (ph ? i0 : i1) * 200);
            float acc = 0.0f;
#pragma unroll
            for (int q = 0; q < 25; q++) {
                float4 w = wp4[q], x = xp[q];
                acc += w.x * x.x + w.y * x.y + w.z * x.z + w.w * x.w;
            }
            unsigned msk = __activemask();
            acc += __shfl_xor_sync(msk, acc, 1);
            if (!ph) sG[r] = acc + sBt[r];
        }
        // warps 8,9: score GEMV, one row per warp (shorter dependency chain)
        if (warp == 8 || warp == 9) {
            int row = warp - 8;
            const float* w = sWa + row * 600;
            const float* f1p = sBuf + i1 * 200;
            const float* f0p = sBuf + i0 * 200;
            const float* fbp = sBuf + ib * 200;
            float a = 0.0f;
#pragma unroll
            for (int it = 0; it < 19; it++) {
                int k = lane + it * 32;
                if (k < 600) {
                    float f = (k < 200) ? f1p[k] : (k < 400) ? f0p[k - 200] : fbp[k - 400];
                    a += w[k] * f;
                }
            }
#pragma unroll
            for (int o = 16; o > 0; o >>= 1) a += __shfl_down_sync(0xffffffffu, a, o);
            if (lane == 0) sSc[row] = a + (row ? ba1 : ba0);
        }
        // warp 10: prefetch stack[sp-3] -> ipre
        if (warp == 10) {
            float4* dpre = (float4*)(sBuf + ipre * 200);
            const float4* mi4 = (const float4*)sMiss;
            for (int q = lane; q < 50; q += 32)
                dpre[q] = (sp >= 3) ? ldcg4(&g_stk[(sp - 3) * ENCD + 4 * q]) : mi4[q];
        }
        // warp 11: prefetch enc[bp+1] -> ibn
        if (warp == 11) {
            float4* dbn = (float4*)(sBuf + ibn * 200);
            const float4* mi4 = (const float4*)sMiss;
            int nbp = bp + 1;
            for (int q = lane; q < 50; q += 32)
                dbn[q] = (nbp < NSEQ) ? __ldg(((const float4*)(g_enc + nbp * ENCD)) + q)
                                      : mi4[q];
        }
        __syncthreads();

        // ==== PHASE B: decision + commit (warp 0 only) ====
        float m0 = (bp < NSEQ) ? sSc[0] : -1e30f;
        float m1 = (sp >= 2)   ? sSc[1] : -1e30f;
        bool is_shift = (m0 >= m1);   // argmax, first-index tie-break

        if (warp == 0) {
            if (is_shift) {
                if (lane < 25) {
                    const float2* src = (const float2*)(sBuf + ib * 200 + (int)rank * 50);
                    stcg2(&g_stk[sp * ENCD + (int)rank * 50 + 2 * lane], src[lane]);
                }
            } else {
                if (lane < 25) {
                    int u = lane;
                    int j = (int)rank * 25 + u;
                    float gi = sG[u],        gf1 = sG[25 + u], gf2 = sG[50 + u];
                    float go = sG[75 + u],   gu  = sG[100 + u];
                    float c1 = sBuf[i1 * 200 + 100 + j];
                    float c2 = sBuf[i0 * 200 + 100 + j];
                    float c = sigf(gf1) * c1 + sigf(gf2) * c2 + sigf(gi) * tanh_acc(gu);
                    float h = sigf(go) * tanh_acc(c);
                    sBuf[isp * 200 + j]       = h;
                    sBuf[isp * 200 + 100 + j] = c;
                    unsigned int ah = sBufA + (unsigned int)(isp * 200 + j) * 4u;
                    unsigned int ac = sBufA + (unsigned int)(isp * 200 + 100 + j) * 4u;
#pragma unroll
                    for (unsigned int rk = 0; rk < PCLUSTER; rk++) {
                        if (rk != rank) { st_remote_f32(ah, rk, h); st_remote_f32(ac, rk, c); }
                    }
                    stcg(&g_stk[(sp - 2) * ENCD + j], h);
                    stcg(&g_stk[(sp - 2) * ENCD + 100 + j], c);
                }
            }
            __syncwarp();
            if (lane < PCLUSTER) mbar_arrive_rank(mbarA, (unsigned int)lane);
        }
        mbar_wait_cta(mbarA, (unsigned int)(step & 1));

        // ---- rotate ring indices (uniform across CTAs) ----
        if (is_shift) {
            int t = i1; i1 = i0; i0 = ib; ib = ibn; ibn = t;
            sp += 1; bp += 1;
        } else {
            int n1 = ipre, n0 = isp;
            ipre = i1; isp = i0;
            i1 = n1; i0 = n0;
            sp -= 1;
        }
    }

    if (rank == 0 && tid < 50) {
        float4 v = ldcg4(&g_stk[4 * tid]);
        ((float4*)out)[tid] = v;
    }
}

// ---------------------------------------------------------------------------
extern "C" void kernel_launch(void* const* d_in, const int* in_sizes, int n_in,
                              void* d_out, int out_size)
{
    const int*   tokens  = (const int*)d_in[0];
    const int*   lengths = (const int*)d_in[1];
    const float* emb     = (const float*)d_in[2];
    const float* Wih0    = (const float*)d_in[3];
    const float* Whh0    = (const float*)d_in[4];
    const float* b0      = (const float*)d_in[5];
    const float* Wih12   = (const float*)d_in[6];
    const float* Whh12   = (const float*)d_in[7];
    const float* b12     = (const float*)d_in[8];
    const float* missing = (const float*)d_in[9];
    const float* Wa      = (const float*)d_in[10];
    const float* ba      = (const float*)d_in[11];
    const float* Wt      = (const float*)d_in[12];
    const float* bt      = (const float*)d_in[13];
    float* out = (float*)d_out;

    float *P, *Ya, *Yb, *enc;
    cudaGetSymbolAddress((void**)&P,  g_P);
    cudaGetSymbolAddress((void**)&Ya, g_Ya);
    cudaGetSymbolAddress((void**)&Yb, g_Yb);
    cudaGetSymbolAddress((void**)&enc, g_enc);

    const int lstmSmem = (40000 + 400 + 400 + 1600) * 4;   // 169600
    const int parsSmem = PRS_TOTAL * 4;                    // 111456
    cudaFuncSetAttribute(lstm_rec, cudaFuncAttributeMaxDynamicSharedMemorySize, lstmSmem);
    cudaFuncSetAttribute(parser4, cudaFuncAttributeMaxDynamicSharedMemorySize, parsSmem);

    dim3 gg(128, 10), rg(64, 2);

    // layer 0
    proj_gemm<<<gg, 256>>>(emb, tokens, Wih0, b0, P, 300);
    lstm_rec<<<rg, 400, lstmSmem>>>(P, Whh0, lengths, Ya, nullptr);
    // layer 1
    proj_gemm<<<gg, 256>>>(Ya, nullptr, Wih12, b12, P, 200);
    lstm_rec<<<rg, 400, lstmSmem>>>(P, Whh12, lengths, Yb, nullptr);
    // layer 2 (+ fused meanpool -> enc)
    proj_gemm<<<gg, 256>>>(Yb, nullptr, Wih12 + 160000, b12 + 800, P, 200);
    lstm_rec<<<rg, 400, lstmSmem>>>(P, Whh12 + 80000, lengths, nullptr, enc);
    // parse
    parser4<<<PCLUSTER, PR_THREADS, parsSmem>>>(missing, Wa, ba, Wt, bt, out);
}

// round 9
// speedup vs baseline: 1.0425x; 1.0425x over previous
#include <cuda_runtime.h>
#include <stdint.h>
#include <math.h>

#define NSEQ 256
#define TLEN 32
#define MROWS 8192      // NSEQ*TLEN
#define ENCD 200

// scratch (static device allocations are allowed)
__device__ float g_P  [MROWS * 800];
__device__ float g_Ya [MROWS * ENCD];
__device__ float g_Yb [MROWS * ENCD];
__device__ float g_enc[NSEQ * ENCD];
__device__ float g_stk[NSEQ * ENCD];

__device__ __forceinline__ float sigf(float x) { return 1.0f / (1.0f + expf(-x)); }
// accurate tanh via expf (robust even under fast-math)
__device__ __forceinline__ float tanh_acc(float x) {
    float e = expf(-2.0f * fabsf(x));
    float r = (1.0f - e) / (1.0f + e);
    return x >= 0.0f ? r : -r;
}
__device__ __forceinline__ float4 ldcg4(const float* p) {
    float4 v;
    asm volatile("ld.global.cg.v4.f32 {%0,%1,%2,%3}, [%4];"
                 : "=f"(v.x), "=f"(v.y), "=f"(v.z), "=f"(v.w) : "l"(p));
    return v;
}
__device__ __forceinline__ void stcg(float* p, float v) {
    asm volatile("st.global.cg.f32 [%0], %1;" :: "l"(p), "f"(v));
}
__device__ __forceinline__ void stcg2(float* p, float2 v) {
    asm volatile("st.global.cg.v2.f32 [%0], {%1,%2};"
                 :: "l"(p), "f"(v.x), "f"(v.y));
}
__device__ __forceinline__ unsigned int smem_u32(const void* p) {
    unsigned int a;
    asm("{ .reg .u64 t; cvta.to.shared.u64 t, %1; cvt.u32.u64 %0, t; }"
        : "=r"(a) : "l"(p));
    return a;
}
__device__ __forceinline__ unsigned int ctarank() {
    unsigned int r; asm("mov.u32 %0, %%cluster_ctarank;" : "=r"(r)); return r;
}
__device__ __forceinline__ void st_remote_f32(unsigned int laddr, unsigned int rk, float v) {
    asm volatile(
        "{ .reg .b32 ra; mapa.shared::cluster.u32 ra, %0, %1; "
        "st.shared::cluster.f32 [ra], %2; }"
        :: "r"(laddr), "r"(rk), "f"(v) : "memory");
}
__device__ __forceinline__ void mbar_init(unsigned int addr, unsigned int count) {
    asm volatile("mbarrier.init.shared.b64 [%0], %1;" :: "r"(addr), "r"(count) : "memory");
}
// remote (or self) arrive, release.cluster semantics (default)
__device__ __forceinline__ void mbar_arrive_rank(unsigned int laddr, unsigned int rk) {
    asm volatile(
        "{ .reg .b32 ra; mapa.shared::cluster.u32 ra, %0, %1; "
        "mbarrier.arrive.shared::cluster.b64 _, [ra]; }"
        :: "r"(laddr), "r"(rk) : "memory");
}
// acquire at CLUSTER scope folded into the wait
__device__ __forceinline__ void mbar_wait_cl(unsigned int addr, unsigned int parity) {
    asm volatile(
        "{\n\t.reg .pred P1;\n\t"
        "WL%=:\n\t"
        "mbarrier.try_wait.parity.acquire.cluster.shared::cta.b64 P1, [%0], %1, 0x989680;\n\t"
        "@P1 bra.uni WD%=;\n\t"
        "bra.uni WL%=;\n\t"
        "WD%=:\n\t}"
        :: "r"(addr), "r"(parity) : "memory");
}

// ---------------------------------------------------------------------------
// P[m][800] = A[row(m)][0:K] @ W[n][0:K]^T + bias[n]
// BM=128, BN=80, BK=20, 256 threads, 8x5 micro-tile (40 FFMA / 7 LDS-ops per k)
// ---------------------------------------------------------------------------
__global__ __launch_bounds__(256) void proj_gemm(
    const float* __restrict__ Asrc, const int* __restrict__ tok,
    const float* __restrict__ W, const float* __restrict__ bias,
    float* __restrict__ P, int K)
{
    __shared__ float As[20][132];   // k-major, 128 rows + 4 pad
    __shared__ float Ws[20][80];
    __shared__ long long roff[128];

    const int tid = threadIdx.x;
    const int M0 = blockIdx.x * 128;
    const int N0 = blockIdx.y * 80;

    if (tid < 128) {
        long long o = tok ? (long long)__ldg(&tok[M0 + tid]) * (long long)K
                          : (long long)(M0 + tid) * (long long)K;
        roff[tid] = o;
    }
    const int m0 = (tid >> 4) * 8;
    const int n0 = (tid & 15) * 5;

    float acc[8][5];
#pragma unroll
    for (int i = 0; i < 8; i++)
#pragma unroll
        for (int j = 0; j < 5; j++) acc[i][j] = 0.0f;
    __syncthreads();

    for (int kt = 0; kt < K; kt += 20) {
        // A tile: 128 rows x 20 k = 2560 elements, 10 per thread (2 halves of 5)
#pragma unroll
        for (int half = 0; half < 2; half++) {
            int i0 = (tid + half * 256) * 5;
            int mm = i0 / 20, kk = i0 % 20;
            const float* ap = Asrc + roff[mm] + kt + kk;
#pragma unroll
            for (int q = 0; q < 5; q++) As[kk + q][mm] = ap[q];
        }
        // W tile: 80 rows x 20 k
        for (int i = tid; i < 1600; i += 256) {
            int nn = i / 20, kk = i % 20;
            Ws[kk][nn] = __ldg(&W[(size_t)(N0 + nn) * K + kt + kk]);
        }
        __syncthreads();
#pragma unroll
        for (int kk = 0; kk < 20; kk++) {
            float4 a4lo = *(const float4*)&As[kk][m0];
            float4 a4hi = *(const float4*)&As[kk][m0 + 4];
            float a[8] = {a4lo.x, a4lo.y, a4lo.z, a4lo.w,
                          a4hi.x, a4hi.y, a4hi.z, a4hi.w};
            float b[5];
#pragma unroll
            for (int j = 0; j < 5; j++) b[j] = Ws[kk][n0 + j];
#pragma unroll
            for (int i = 0; i < 8; i++)
#pragma unroll
                for (int j = 0; j < 5; j++) acc[i][j] += a[i] * b[j];
        }
        __syncthreads();
    }
#pragma unroll
    for (int i = 0; i < 8; i++) {
        size_t row = (size_t)(M0 + m0 + i) * 800 + N0 + n0;
#pragma unroll
        for (int j = 0; j < 5; j++)
            P[row + j] = acc[i][j] + __ldg(&bias[N0 + n0 + j]);
    }
}

// ---------------------------------------------------------------------------
// LSTM recurrence (400 threads, pipelined P loads, 2 partial accumulators
// per gate to halve the FFMA dependency chain). If encOut != null (final
// layer), skip Y writes and emit mean-pooled enc directly.
// ---------------------------------------------------------------------------
__global__ __launch_bounds__(400, 1) void lstm_rec(
    const float* __restrict__ P, const float* __restrict__ Whh2,
    const int* __restrict__ lengths, float* __restrict__ Y,
    float* __restrict__ encOut)
{
    extern __shared__ float sm[];
    float* sW = sm;
    float* sH = sm + 40000;
    float* sC = sH + 400;
    float* sG = sC + 400;

    const int tid = threadIdx.x;
    const int dir = blockIdx.y;
    const int sq0 = blockIdx.x * 4;

    const float* Wd = Whh2 + dir * 40000;
    for (int i = tid; i < 40000; i += 400) sW[i] = Wd[i];
    for (int i = tid; i < 800; i += 400) sm[40000 + i] = 0.0f;

    const int sPW = tid / 100;
    const int jPW = tid % 100;
    const int myLen = __ldg(&lengths[sq0 + sPW]);
    __syncthreads();

    const float4* sW4 = (const float4*)(sW + tid * 100);
    const float4* sH4 = (const float4*)sH;

    float p0, p1, p2, p3;
    {
        int t = dir ? (TLEN - 1) : 0;
        size_t base = ((size_t)sq0 * TLEN + t) * 800 + dir * 400 + tid;
        p0 = __ldg(&P[base]);
        p1 = __ldg(&P[base + 1 * TLEN * 800]);
        p2 = __ldg(&P[base + 2 * TLEN * 800]);
        p3 = __ldg(&P[base + 3 * TLEN * 800]);
    }
    float hsum = 0.0f;

    for (int st = 0; st < TLEN; st++) {
        int t = dir ? (TLEN - 1 - st) : st;
        float a0 = 0.f, a1 = 0.f, a2 = 0.f, a3 = 0.f;   // xy partials
        float b0 = 0.f, b1 = 0.f, b2 = 0.f, b3 = 0.f;   // zw partials
        float q0 = p0, q1 = p1, q2 = p2, q3 = p3;
        if (st + 1 < TLEN) {
            int tn = dir ? (TLEN - 2 - st) : (st + 1);
            size_t base = ((size_t)sq0 * TLEN + tn) * 800 + dir * 400 + tid;
            p0 = __ldg(&P[base]);
            p1 = __ldg(&P[base + 1 * TLEN * 800]);
            p2 = __ldg(&P[base + 2 * TLEN * 800]);
            p3 = __ldg(&P[base + 3 * TLEN * 800]);
        }
#pragma unroll
        for (int kq = 0; kq < 25; kq++) {
            float4 w = sW4[kq];
            float4 h0 = sH4[kq], h1 = sH4[25 + kq], h2 = sH4[50 + kq], h3 = sH4[75 + kq];
            a0 += w.x * h0.x + w.y * h0.y;  b0 += w.z * h0.z + w.w * h0.w;
            a1 += w.x * h1.x + w.y * h1.y;  b1 += w.z * h1.z + w.w * h1.w;
            a2 += w.x * h2.x + w.y * h2.y;  b2 += w.z * h2.z + w.w * h2.w;
            a3 += w.x * h3.x + w.y * h3.y;  b3 += w.z * h3.z + w.w * h3.w;
        }
        sG[tid]        = q0 + a0 + b0;
        sG[400 + tid]  = q1 + a1 + b1;
        sG[800 + tid]  = q2 + a2 + b2;
        sG[1200 + tid] = q3 + a3 + b3;
        __syncthreads();
        {
            float gi = sG[sPW * 400 + jPW];
            float gf = sG[sPW * 400 + 100 + jPW];
            float gg = sG[sPW * 400 + 200 + jPW];
            float go = sG[sPW * 400 + 300 + jPW];
            float c  = sC[sPW * 100 + jPW];
            float cn = sigf(gf) * c + sigf(gi) * tanh_acc(gg);
            float hn = sigf(go) * tanh_acc(cn);
            float outv = 0.0f;
            if (t < myLen) {
                sC[sPW * 100 + jPW] = cn;
                sH[sPW * 100 + jPW] = hn;
                outv = hn;
            }
            if (encOut) hsum += outv;
            else Y[((size_t)(sq0 + sPW) * TLEN + t) * ENCD + dir * 100 + jPW] = outv;
        }
        __syncthreads();
    }
    if (encOut)
        encOut[(sq0 + sPW) * ENCD + dir * 100 + jPW] = hsum / (float)myLen;
}

// ---------------------------------------------------------------------------
// Parser: round-6 configuration (best measured). 4-CTA cluster, 320 threads.
// Warps 0-7 speculative gate GEMV; warp 8 score; warp 9 prefetch.
// Commit tid<25, __syncthreads, arrives tid<4, acquire.cluster wait.
// ---------------------------------------------------------------------------
#define PRS_WT    0
#define PRS_WA    25000
#define PRS_BT    26200
#define PRS_BUF   26328
#define PRS_G     27528
#define PRS_MISS  27656
#define PRS_SC    27856
#define PRS_MBAR  27860
#define PRS_TOTAL 27864
#define PR_THREADS 320
#define PCLUSTER 4

__global__ __cluster_dims__(PCLUSTER, 1, 1) __launch_bounds__(PR_THREADS, 1) void parser4(
    const float* __restrict__ missing, const float* __restrict__ Wa,
    const float* __restrict__ ba, const float* __restrict__ Wt,
    const float* __restrict__ bt, float* __restrict__ out)
{
    extern __shared__ float sm[];
    float* sWt   = sm + PRS_WT;    // 125 rows x 200
    float* sWa   = sm + PRS_WA;    // 1200
    float* sBt   = sm + PRS_BT;    // 125
    float* sBuf  = sm + PRS_BUF;   // 6 x 200
    float* sG    = sm + PRS_G;     // 125
    float* sMiss = sm + PRS_MISS;  // 200
    float* sSc   = sm + PRS_SC;    // 2
    const int tid = threadIdx.x;
    const unsigned int rank = ctarank();
    const unsigned int mbarA = smem_u32(sm + PRS_MBAR);
    const unsigned int sBufA = smem_u32(sBuf);

    for (int i = tid; i < 125 * 200; i += PR_THREADS) {
        int r = i / 200, k = i - r * 200;
        int grow = (r / 25) * 100 + (int)rank * 25 + (r % 25);
        sWt[i] = __ldg(&Wt[grow * 200 + k]);
    }
    for (int i = tid; i < 1200; i += PR_THREADS) sWa[i] = __ldg(&Wa[i]);
    if (tid < 125) {
        int grow = (tid / 25) * 100 + (int)rank * 25 + (tid % 25);
        sBt[tid] = __ldg(&bt[grow]);
    }
    if (tid < 200) {
        float mv = __ldg(&missing[tid]);
        sMiss[tid] = mv;
        sBuf[0 * 200 + tid] = mv;                    // i1 = missing
        sBuf[1 * 200 + tid] = mv;                    // i0 = missing
        sBuf[2 * 200 + tid] = __ldg(&g_enc[tid]);    // ib = enc[0]
    }
    const float ba0 = __ldg(&ba[0]), ba1 = __ldg(&ba[1]);
    if (tid == 0) mbar_init(mbarA, PCLUSTER);
    __syncthreads();
    asm volatile("barrier.cluster.arrive.aligned;" ::: "memory");
    asm volatile("barrier.cluster.wait.aligned;"   ::: "memory");

    int i1 = 0, i0 = 1, ib = 2, ipre = 3, ibn = 4, isp = 5;
    int sp = 0, bp = 0;
    const int warp = tid >> 5;

    for (int step = 0; step < 2 * NSEQ - 1; step++) {
        // ==== PHASE A ====
        if (tid < 250) {
            int r = tid >> 1, ph = tid & 1;
            const float4* wp4 = (const float4*)(sWt + r * 200 + ph * 100);
            const float4* xp  = (const float4*)(sBuf + (ph ? i0 : i1) * 200);
            float acc = 0.0f;
#pragma unroll
            for (int q = 0; q < 25; q++) {
                float4 w = wp4[q], x = xp[q];
                acc += w.x * x.x + w.y * x.y + w.z * x.z + w.w * x.w;
            }
            unsigned msk = __activemask();
            acc += __shfl_xor_sync(msk, acc, 1);
            if (!ph) sG[r] = acc + sBt[r];
        }
        if (warp == 8) {
            int lane = tid - 256;
            const float* w0 = sWa;
            const float* w1 = sWa + 600;
            const float* f1p = sBuf + i1 * 200;
            const float* f0p = sBuf + i0 * 200;
            const float* fbp = sBuf + ib * 200;
            float a0 = 0.0f, a1 = 0.0f;
#pragma unroll
            for (int k = 0; k < 7; k++) {
                int kk = lane + 32 * k;
                if (kk < 200) { float f = f1p[kk]; a0 += w0[kk] * f;       a1 += w1[kk] * f; }
            }
#pragma unroll
            for (int k = 0; k < 7; k++) {
                int kk = lane + 32 * k;
                if (kk < 200) { float f = f0p[kk]; a0 += w0[200 + kk] * f; a1 += w1[200 + kk] * f; }
            }
#pragma unroll
            for (int k = 0; k < 7; k++) {
                int kk = lane + 32 * k;
                if (kk < 200) { float f = fbp[kk]; a0 += w0[400 + kk] * f; a1 += w1[400 + kk] * f; }
            }
#pragma unroll
            for (int o = 16; o > 0; o >>= 1) {
                a0 += __shfl_down_sync(0xffffffffu, a0, o);
                a1 += __shfl_down_sync(0xffffffffu, a1, o);
            }
            if (lane == 0) { sSc[0] = a0 + ba0; sSc[1] = a1 + ba1; }
        }
        if (warp == 9) {
            int lane = tid - 288;
            float4* dpre = (float4*)(sBuf + ipre * 200);
            float4* dbn  = (float4*)(sBuf + ibn  * 200);
            const float4* mi4 = (const float4*)sMiss;
            for (int q = lane; q < 50; q += 32)
                dpre[q] = (sp >= 3) ? ldcg4(&g_stk[(sp - 3) * ENCD + 4 * q]) : mi4[q];
            int nbp = bp + 1;
            for (int q = lane; q < 50; q += 32)
                dbn[q] = (nbp < NSEQ) ? __ldg(((const float4*)(g_enc + nbp * ENCD)) + q)
                                      : mi4[q];
        }
        __syncthreads();

        // ==== PHASE B ====
        float m0 = (bp < NSEQ) ? sSc[0] : -1e30f;
        float m1 = (sp >= 2)   ? sSc[1] : -1e30f;
        bool is_shift = (m0 >= m1);   // argmax, first-index tie-break

        if (is_shift) {
            if (tid < 25) {
                const float2* src = (const float2*)(sBuf + ib * 200 + (int)rank * 50);
                stcg2(&g_stk[sp * ENCD + (int)rank * 50 + 2 * tid], src[tid]);
            }
        } else {
            if (tid < 25) {
                int u = tid;
                int j = (int)rank * 25 + u;
                float gi = sG[u],        gf1 = sG[25 + u], gf2 = sG[50 + u];
                float go = sG[75 + u],   gu  = sG[100 + u];
                float c1 = sBuf[i1 * 200 + 100 + j];
                float c2 = sBuf[i0 * 200 + 100 + j];
                float c = sigf(gf1) * c1 + sigf(gf2) * c2 + sigf(gi) * tanh_acc(gu);
                float h = sigf(go) * tanh_acc(c);
                sBuf[isp * 200 + j]       = h;
                sBuf[isp * 200 + 100 + j] = c;
                unsigned int ah = sBufA + (unsigned int)(isp * 200 + j) * 4u;
                unsigned int ac = sBufA + (unsigned int)(isp * 200 + 100 + j) * 4u;
#pragma unroll
                for (unsigned int rk = 0; rk < PCLUSTER; rk++) {
                    if (rk != rank) { st_remote_f32(ah, rk, h); st_remote_f32(ac, rk, c); }
                }
                stcg(&g_stk[(sp - 2) * ENCD + j], h);
                stcg(&g_stk[(sp - 2) * ENCD + 100 + j], c);
            }
        }
        __syncthreads();
        if (tid < PCLUSTER) mbar_arrive_rank(mbarA, (unsigned int)tid);
        mbar_wait_cl(mbarA, (unsigned int)(step & 1));

        if (is_shift) {
            int t = i1; i1 = i0; i0 = ib; ib = ibn; ibn = t;
            sp += 1; bp += 1;
        } else {
            int n1 = ipre, n0 = isp;
            ipre = i1; isp = i0;
            i1 = n1; i0 = n0;
            sp -= 1;
        }
    }

    if (rank == 0 && tid < 50) {
        float4 v = ldcg4(&g_stk[4 * tid]);
        ((float4*)out)[tid] = v;
    }
}

// ---------------------------------------------------------------------------
extern "C" void kernel_launch(void* const* d_in, const int* in_sizes, int n_in,
                              void* d_out, int out_size)
{
    const int*   tokens  = (const int*)d_in[0];
    const int*   lengths = (const int*)d_in[1];
    const float* emb     = (const float*)d_in[2];
    const float* Wih0    = (const float*)d_in[3];
    const float* Whh0    = (const float*)d_in[4];
    const float* b0      = (const float*)d_in[5];
    const float* Wih12   = (const float*)d_in[6];
    const float* Whh12   = (const float*)d_in[7];
    const float* b12     = (const float*)d_in[8];
    const float* missing = (const float*)d_in[9];
    const float* Wa      = (const float*)d_in[10];
    const float* ba      = (const float*)d_in[11];
    const float* Wt      = (const float*)d_in[12];
    const float* bt      = (const float*)d_in[13];
    float* out = (float*)d_out;

    float *P, *Ya, *Yb, *enc;
    cudaGetSymbolAddress((void**)&P,  g_P);
    cudaGetSymbolAddress((void**)&Ya, g_Ya);
    cudaGetSymbolAddress((void**)&Yb, g_Yb);
    cudaGetSymbolAddress((void**)&enc, g_enc);

    const int lstmSmem = (40000 + 400 + 400 + 1600) * 4;   // 169600
    const int parsSmem = PRS_TOTAL * 4;                    // 111456
    cudaFuncSetAttribute(lstm_rec, cudaFuncAttributeMaxDynamicSharedMemorySize, lstmSmem);
    cudaFuncSetAttribute(parser4, cudaFuncAttributeMaxDynamicSharedMemorySize, parsSmem);

    dim3 gg(64, 10), rg(64, 2);

    // layer 0
    proj_gemm<<<gg, 256>>>(emb, tokens, Wih0, b0, P, 300);
    lstm_rec<<<rg, 400, lstmSmem>>>(P, Whh0, lengths, Ya, nullptr);
    // layer 1
    proj_gemm<<<gg, 256>>>(Ya, nullptr, Wih12, b12, P, 200);
    lstm_rec<<<rg, 400, lstmSmem>>>(P, Whh12, lengths, Yb, nullptr);
    // layer 2 (+ fused meanpool -> enc)
    proj_gemm<<<gg, 256>>>(Yb, nullptr, Wih12 + 160000, b12 + 800, P, 200);
    lstm_rec<<<rg, 400, lstmSmem>>>(P, Whh12 + 80000, lengths, nullptr, enc);
    // parse
    parser4<<<PCLUSTER, PR_THREADS, parsSmem>>>(missing, Wa, ba, Wt, bt, out);
}

// round 10
// speedup vs baseline: 1.0537x; 1.0107x over previous
#include <cuda_runtime.h>
#include <stdint.h>
#include <math.h>

#define NSEQ 256
#define TLEN 32
#define MROWS 8192      // NSEQ*TLEN
#define ENCD 200

// scratch (static device allocations are allowed)
__device__ float g_P  [MROWS * 800];
__device__ float g_Ya [MROWS * ENCD];
__device__ float g_Yb [MROWS * ENCD];
__device__ float g_enc[NSEQ * ENCD];
__device__ float g_stk[NSEQ * ENCD];

__device__ __forceinline__ float sigf(float x) { return 1.0f / (1.0f + expf(-x)); }
// accurate tanh via expf (robust even under fast-math)
__device__ __forceinline__ float tanh_acc(float x) {
    float e = expf(-2.0f * fabsf(x));
    float r = (1.0f - e) / (1.0f + e);
    return x >= 0.0f ? r : -r;
}
__device__ __forceinline__ float4 ldcg4(const float* p) {
    float4 v;
    asm volatile("ld.global.cg.v4.f32 {%0,%1,%2,%3}, [%4];"
                 : "=f"(v.x), "=f"(v.y), "=f"(v.z), "=f"(v.w) : "l"(p));
    return v;
}
__device__ __forceinline__ void stcg(float* p, float v) {
    asm volatile("st.global.cg.f32 [%0], %1;" :: "l"(p), "f"(v));
}
__device__ __forceinline__ void stcg2(float* p, float2 v) {
    asm volatile("st.global.cg.v2.f32 [%0], {%1,%2};"
                 :: "l"(p), "f"(v.x), "f"(v.y));
}
__device__ __forceinline__ unsigned int smem_u32(const void* p) {
    unsigned int a;
    asm("{ .reg .u64 t; cvta.to.shared.u64 t, %1; cvt.u32.u64 %0, t; }"
        : "=r"(a) : "l"(p));
    return a;
}
__device__ __forceinline__ unsigned int ctarank() {
    unsigned int r; asm("mov.u32 %0, %%cluster_ctarank;" : "=r"(r)); return r;
}
__device__ __forceinline__ void st_remote_f32(unsigned int laddr, unsigned int rk, float v) {
    asm volatile(
        "{ .reg .b32 ra; mapa.shared::cluster.u32 ra, %0, %1; "
        "st.shared::cluster.f32 [ra], %2; }"
        :: "r"(laddr), "r"(rk), "f"(v) : "memory");
}
__device__ __forceinline__ void mbar_init(unsigned int addr, unsigned int count) {
    asm volatile("mbarrier.init.shared.b64 [%0], %1;" :: "r"(addr), "r"(count) : "memory");
}
// remote (or self) arrive, release.cluster semantics (default)
__device__ __forceinline__ void mbar_arrive_rank(unsigned int laddr, unsigned int rk) {
    asm volatile(
        "{ .reg .b32 ra; mapa.shared::cluster.u32 ra, %0, %1; "
        "mbarrier.arrive.shared::cluster.b64 _, [ra]; }"
        :: "r"(laddr), "r"(rk) : "memory");
}
// CTA-scope acquire wait. Safe here: peer data arrives via DSMEM stores into
// OUR smem (not L1-cached) and via .cg<->.cg global traffic (L2-coherent);
// g_enc is read-only during the parser. Avoids any per-wait L1 invalidate.
__device__ __forceinline__ void mbar_wait_cta(unsigned int addr, unsigned int parity) {
    asm volatile(
        "{\n\t.reg .pred P1;\n\t"
        "WL%=:\n\t"
        "mbarrier.try_wait.parity.acquire.cta.shared::cta.b64 P1, [%0], %1, 0x989680;\n\t"
        "@P1 bra.uni WD%=;\n\t"
        "bra.uni WL%=;\n\t"
        "WD%=:\n\t}"
        :: "r"(addr), "r"(parity) : "memory");
}

// ---------------------------------------------------------------------------
// P[m][800] = A[row(m)][0:K] @ W[n][0:K]^T + bias[n]
// BM=128, BN=80, BK=20, 256 threads, 8x5 micro-tile
// ---------------------------------------------------------------------------
__global__ __launch_bounds__(256) void proj_gemm(
    const float* __restrict__ Asrc, const int* __restrict__ tok,
    const float* __restrict__ W, const float* __restrict__ bias,
    float* __restrict__ P, int K)
{
    __shared__ float As[20][132];   // k-major, 128 rows + 4 pad
    __shared__ float Ws[20][80];
    __shared__ long long roff[128];

    const int tid = threadIdx.x;
    const int M0 = blockIdx.x * 128;
    const int N0 = blockIdx.y * 80;

    if (tid < 128) {
        long long o = tok ? (long long)__ldg(&tok[M0 + tid]) * (long long)K
                          : (long long)(M0 + tid) * (long long)K;
        roff[tid] = o;
    }
    const int m0 = (tid >> 4) * 8;
    const int n0 = (tid & 15) * 5;

    float acc[8][5];
#pragma unroll
    for (int i = 0; i < 8; i++)
#pragma unroll
        for (int j = 0; j < 5; j++) acc[i][j] = 0.0f;
    __syncthreads();

    for (int kt = 0; kt < K; kt += 20) {
#pragma unroll
        for (int half = 0; half < 2; half++) {
            int i0 = (tid + half * 256) * 5;
            int mm = i0 / 20, kk = i0 % 20;
            const float* ap = Asrc + roff[mm] + kt + kk;
#pragma unroll
            for (int q = 0; q < 5; q++) As[kk + q][mm] = ap[q];
        }
        for (int i = tid; i < 1600; i += 256) {
            int nn = i / 20, kk = i % 20;
            Ws[kk][nn] = __ldg(&W[(size_t)(N0 + nn) * K + kt + kk]);
        }
        __syncthreads();
#pragma unroll
        for (int kk = 0; kk < 20; kk++) {
            float4 a4lo = *(const float4*)&As[kk][m0];
            float4 a4hi = *(const float4*)&As[kk][m0 + 4];
            float a[8] = {a4lo.x, a4lo.y, a4lo.z, a4lo.w,
                          a4hi.x, a4hi.y, a4hi.z, a4hi.w};
            float b[5];
#pragma unroll
            for (int j = 0; j < 5; j++) b[j] = Ws[kk][n0 + j];
#pragma unroll
            for (int i = 0; i < 8; i++)
#pragma unroll
                for (int j = 0; j < 5; j++) acc[i][j] += a[i] * b[j];
        }
        __syncthreads();
    }
#pragma unroll
    for (int i = 0; i < 8; i++) {
        size_t row = (size_t)(M0 + m0 + i) * 800 + N0 + n0;
#pragma unroll
        for (int j = 0; j < 5; j++)
            P[row + j] = acc[i][j] + __ldg(&bias[N0 + n0 + j]);
    }
}

// ---------------------------------------------------------------------------
// LSTM recurrence (400 threads, pipelined P loads, single accumulators —
// best measured variant). If encOut != null, fuse mean-pool, skip Y.
// ---------------------------------------------------------------------------
__global__ __launch_bounds__(400, 1) void lstm_rec(
    const float* __restrict__ P, const float* __restrict__ Whh2,
    const int* __restrict__ lengths, float* __restrict__ Y,
    float* __restrict__ encOut)
{
    extern __shared__ float sm[];
    float* sW = sm;
    float* sH = sm + 40000;
    float* sC = sH + 400;
    float* sG = sC + 400;

    const int tid = threadIdx.x;
    const int dir = blockIdx.y;
    const int sq0 = blockIdx.x * 4;

    const float* Wd = Whh2 + dir * 40000;
    for (int i = tid; i < 40000; i += 400) sW[i] = Wd[i];
    for (int i = tid; i < 800; i += 400) sm[40000 + i] = 0.0f;

    const int sPW = tid / 100;
    const int jPW = tid % 100;
    const int myLen = __ldg(&lengths[sq0 + sPW]);
    __syncthreads();

    const float4* sW4 = (const float4*)(sW + tid * 100);
    const float4* sH4 = (const float4*)sH;

    float p0, p1, p2, p3;
    {
        int t = dir ? (TLEN - 1) : 0;
        size_t base = ((size_t)sq0 * TLEN + t) * 800 + dir * 400 + tid;
        p0 = __ldg(&P[base]);
        p1 = __ldg(&P[base + 1 * TLEN * 800]);
        p2 = __ldg(&P[base + 2 * TLEN * 800]);
        p3 = __ldg(&P[base + 3 * TLEN * 800]);
    }
    float hsum = 0.0f;

    for (int st = 0; st < TLEN; st++) {
        int t = dir ? (TLEN - 1 - st) : st;
        float acc0 = p0, acc1 = p1, acc2 = p2, acc3 = p3;
        if (st + 1 < TLEN) {
            int tn = dir ? (TLEN - 2 - st) : (st + 1);
            size_t base = ((size_t)sq0 * TLEN + tn) * 800 + dir * 400 + tid;
            p0 = __ldg(&P[base]);
            p1 = __ldg(&P[base + 1 * TLEN * 800]);
            p2 = __ldg(&P[base + 2 * TLEN * 800]);
            p3 = __ldg(&P[base + 3 * TLEN * 800]);
        }
#pragma unroll
        for (int kq = 0; kq < 25; kq++) {
            float4 w = sW4[kq];
            float4 h0 = sH4[kq], h1 = sH4[25 + kq], h2 = sH4[50 + kq], h3 = sH4[75 + kq];
            acc0 += w.x * h0.x + w.y * h0.y + w.z * h0.z + w.w * h0.w;
            acc1 += w.x * h1.x + w.y * h1.y + w.z * h1.z + w.w * h1.w;
            acc2 += w.x * h2.x + w.y * h2.y + w.z * h2.z + w.w * h2.w;
            acc3 += w.x * h3.x + w.y * h3.y + w.z * h3.z + w.w * h3.w;
        }
        sG[tid] = acc0; sG[400 + tid] = acc1; sG[800 + tid] = acc2; sG[1200 + tid] = acc3;
        __syncthreads();
        {
            float gi = sG[sPW * 400 + jPW];
            float gf = sG[sPW * 400 + 100 + jPW];
            float gg = sG[sPW * 400 + 200 + jPW];
            float go = sG[sPW * 400 + 300 + jPW];
            float c  = sC[sPW * 100 + jPW];
            float cn = sigf(gf) * c + sigf(gi) * tanh_acc(gg);
            float hn = sigf(go) * tanh_acc(cn);
            float outv = 0.0f;
            if (t < myLen) {
                sC[sPW * 100 + jPW] = cn;
                sH[sPW * 100 + jPW] = hn;
                outv = hn;
            }
            if (encOut) hsum += outv;
            else Y[((size_t)(sq0 + sPW) * TLEN + t) * ENCD + dir * 100 + jPW] = outv;
        }
        __syncthreads();
    }
    if (encOut)
        encOut[(sq0 + sPW) * ENCD + dir * 100 + jPW] = hsum / (float)myLen;
}

// ---------------------------------------------------------------------------
// Parser: round-6 structure (best measured), with ONE change: the per-step
// mbarrier wait uses acquire.cta instead of acquire.cluster.
// ---------------------------------------------------------------------------
#define PRS_WT    0
#define PRS_WA    25000
#define PRS_BT    26200
#define PRS_BUF   26328
#define PRS_G     27528
#define PRS_MISS  27656
#define PRS_SC    27856
#define PRS_MBAR  27860
#define PRS_TOTAL 27864
#define PR_THREADS 320
#define PCLUSTER 4

__global__ __cluster_dims__(PCLUSTER, 1, 1) __launch_bounds__(PR_THREADS, 1) void parser4(
    const float* __restrict__ missing, const float* __restrict__ Wa,
    const float* __restrict__ ba, const float* __restrict__ Wt,
    const float* __restrict__ bt, float* __restrict__ out)
{
    extern __shared__ float sm[];
    float* sWt   = sm + PRS_WT;    // 125 rows x 200
    float* sWa   = sm + PRS_WA;    // 1200
    float* sBt   = sm + PRS_BT;    // 125
    float* sBuf  = sm + PRS_BUF;   // 6 x 200
    float* sG    = sm + PRS_G;     // 125
    float* sMiss = sm + PRS_MISS;  // 200
    float* sSc   = sm + PRS_SC;    // 2
    const int tid = threadIdx.x;
    const unsigned int rank = ctarank();
    const unsigned int mbarA = smem_u32(sm + PRS_MBAR);
    const unsigned int sBufA = smem_u32(sBuf);

    for (int i = tid; i < 125 * 200; i += PR_THREADS) {
        int r = i / 200, k = i - r * 200;
        int grow = (r / 25) * 100 + (int)rank * 25 + (r % 25);
        sWt[i] = __ldg(&Wt[grow * 200 + k]);
    }
    for (int i = tid; i < 1200; i += PR_THREADS) sWa[i] = __ldg(&Wa[i]);
    if (tid < 125) {
        int grow = (tid / 25) * 100 + (int)rank * 25 + (tid % 25);
        sBt[tid] = __ldg(&bt[grow]);
    }
    if (tid < 200) {
        float mv = __ldg(&missing[tid]);
        sMiss[tid] = mv;
        sBuf[0 * 200 + tid] = mv;                    // i1 = missing
        sBuf[1 * 200 + tid] = mv;                    // i0 = missing
        sBuf[2 * 200 + tid] = __ldg(&g_enc[tid]);    // ib = enc[0]
    }
    const float ba0 = __ldg(&ba[0]), ba1 = __ldg(&ba[1]);
    if (tid == 0) mbar_init(mbarA, PCLUSTER);
    __syncthreads();
    asm volatile("barrier.cluster.arrive.aligned;" ::: "memory");
    asm volatile("barrier.cluster.wait.aligned;"   ::: "memory");

    int i1 = 0, i0 = 1, ib = 2, ipre = 3, ibn = 4, isp = 5;
    int sp = 0, bp = 0;
    const int warp = tid >> 5;

    for (int step = 0; step < 2 * NSEQ - 1; step++) {
        // ==== PHASE A: independent work in parallel ====
        if (tid < 250) {
            int r = tid >> 1, ph = tid & 1;
            const float4* wp4 = (const float4*)(sWt + r * 200 + ph * 100);
            const float4* xp  = (const float4*)(sBuf + (ph ? i0 : i1) * 200);
            float acc = 0.0f;
#pragma unroll
            for (int q = 0; q < 25; q++) {
                float4 w = wp4[q], x = xp[q];
                acc += w.x * x.x + w.y * x.y + w.z * x.z + w.w * x.w;
            }
            unsigned msk = __activemask();
            acc += __shfl_xor_sync(msk, acc, 1);
            if (!ph) sG[r] = acc + sBt[r];
        }
        if (warp == 8) {
            int lane = tid - 256;
            const float* w0 = sWa;
            const float* w1 = sWa + 600;
            const float* f1p = sBuf + i1 * 200;
            const float* f0p = sBuf + i0 * 200;
            const float* fbp = sBuf + ib * 200;
            float a0 = 0.0f, a1 = 0.0f;
#pragma unroll
            for (int k = 0; k < 7; k++) {
                int kk = lane + 32 * k;
                if (kk < 200) { float f = f1p[kk]; a0 += w0[kk] * f;       a1 += w1[kk] * f; }
            }
#pragma unroll
            for (int k = 0; k < 7; k++) {
                int kk = lane + 32 * k;
                if (kk < 200) { float f = f0p[kk]; a0 += w0[200 + kk] * f; a1 += w1[200 + kk] * f; }
            }
#pragma unroll
            for (int k = 0; k < 7; k++) {
                int kk = lane + 32 * k;
                if (kk < 200) { float f = fbp[kk]; a0 += w0[400 + kk] * f; a1 += w1[400 + kk] * f; }
            }
#pragma unroll
            for (int o = 16; o > 0; o >>= 1) {
                a0 += __shfl_down_sync(0xffffffffu, a0, o);
                a1 += __shfl_down_sync(0xffffffffu, a1, o);
            }
            if (lane == 0) { sSc[0] = a0 + ba0; sSc[1] = a1 + ba1; }
        }
        if (warp == 9) {
            int lane = tid - 288;
            float4* dpre = (float4*)(sBuf + ipre * 200);
            float4* dbn  = (float4*)(sBuf + ibn  * 200);
            const float4* mi4 = (const float4*)sMiss;
            for (int q = lane; q < 50; q += 32)
                dpre[q] = (sp >= 3) ? ldcg4(&g_stk[(sp - 3) * ENCD + 4 * q]) : mi4[q];
            int nbp = bp + 1;
            for (int q = lane; q < 50; q += 32)
                dbn[q] = (nbp < NSEQ) ? __ldg(((const float4*)(g_enc + nbp * ENCD)) + q)
                                      : mi4[q];
        }
        __syncthreads();

        // ==== PHASE B: decision + commit ====
        float m0 = (bp < NSEQ) ? sSc[0] : -1e30f;
        float m1 = (sp >= 2)   ? sSc[1] : -1e30f;
        bool is_shift = (m0 >= m1);   // argmax, first-index tie-break

        if (is_shift) {
            if (tid < 25) {
                const float2* src = (const float2*)(sBuf + ib * 200 + (int)rank * 50);
                stcg2(&g_stk[sp * ENCD + (int)rank * 50 + 2 * tid], src[tid]);
            }
        } else {
            if (tid < 25) {
                int u = tid;
                int j = (int)rank * 25 + u;
                float gi = sG[u],        gf1 = sG[25 + u], gf2 = sG[50 + u];
                float go = sG[75 + u],   gu  = sG[100 + u];
                float c1 = sBuf[i1 * 200 + 100 + j];
                float c2 = sBuf[i0 * 200 + 100 + j];
                float c = sigf(gf1) * c1 + sigf(gf2) * c2 + sigf(gi) * tanh_acc(gu);
                float h = sigf(go) * tanh_acc(c);
                sBuf[isp * 200 + j]       = h;
                sBuf[isp * 200 + 100 + j] = c;
                unsigned int ah = sBufA + (unsigned int)(isp * 200 + j) * 4u;
                unsigned int ac = sBufA + (unsigned int)(isp * 200 + 100 + j) * 4u;
#pragma unroll
                for (unsigned int rk = 0; rk < PCLUSTER; rk++) {
                    if (rk != rank) { st_remote_f32(ah, rk, h); st_remote_f32(ac, rk, c); }
                }
                stcg(&g_stk[(sp - 2) * ENCD + j], h);
                stcg(&g_stk[(sp - 2) * ENCD + 100 + j], c);
            }
        }
        __syncthreads();
        if (tid < PCLUSTER) mbar_arrive_rank(mbarA, (unsigned int)tid);
        mbar_wait_cta(mbarA, (unsigned int)(step & 1));

        if (is_shift) {
            int t = i1; i1 = i0; i0 = ib; ib = ibn; ibn = t;
            sp += 1; bp += 1;
        } else {
            int n1 = ipre, n0 = isp;
            ipre = i1; isp = i0;
            i1 = n1; i0 = n0;
            sp -= 1;
        }
    }

    if (rank == 0 && tid < 50) {
        float4 v = ldcg4(&g_stk[4 * tid]);
        ((float4*)out)[tid] = v;
    }
}

// ---------------------------------------------------------------------------
extern "C" void kernel_launch(void* const* d_in, const int* in_sizes, int n_in,
                              void* d_out, int out_size)
{
    const int*   tokens  = (const int*)d_in[0];
    const int*   lengths = (const int*)d_in[1];
    const float* emb     = (const float*)d_in[2];
    const float* Wih0    = (const float*)d_in[3];
    const float* Whh0    = (const float*)d_in[4];
    const float* b0      = (const float*)d_in[5];
    const float* Wih12   = (const float*)d_in[6];
    const float* Whh12   = (const float*)d_in[7];
    const float* b12     = (const float*)d_in[8];
    const float* missing = (const float*)d_in[9];
    const float* Wa      = (const float*)d_in[10];
    const float* ba      = (const float*)d_in[11];
    const float* Wt      = (const float*)d_in[12];
    const float* bt      = (const float*)d_in[13];
    float* out = (float*)d_out;

    float *P, *Ya, *Yb, *enc;
    cudaGetSymbolAddress((void**)&P,  g_P);
    cudaGetSymbolAddress((void**)&Ya, g_Ya);
    cudaGetSymbolAddress((void**)&Yb, g_Yb);
    cudaGetSymbolAddress((void**)&enc, g_enc);

    const int lstmSmem = (40000 + 400 + 400 + 1600) * 4;   // 169600
    const int parsSmem = PRS_TOTAL * 4;                    // 111456
    cudaFuncSetAttribute(lstm_rec, cudaFuncAttributeMaxDynamicSharedMemorySize, lstmSmem);
    cudaFuncSetAttribute(parser4, cudaFuncAttributeMaxDynamicSharedMemorySize, parsSmem);

    dim3 gg(64, 10), rg(64, 2);

    // layer 0
    proj_gemm<<<gg, 256>>>(emb, tokens, Wih0, b0, P, 300);
    lstm_rec<<<rg, 400, lstmSmem>>>(P, Whh0, lengths, Ya, nullptr);
    // layer 1
    proj_gemm<<<gg, 256>>>(Ya, nullptr, Wih12, b12, P, 200);
    lstm_rec<<<rg, 400, lstmSmem>>>(P, Whh12, lengths, Yb, nullptr);
    // layer 2 (+ fused meanpool -> enc)
    proj_gemm<<<gg, 256>>>(Yb, nullptr, Wih12 + 160000, b12 + 800, P, 200);
    lstm_rec<<<rg, 400, lstmSmem>>>(P, Whh12 + 80000, lengths, nullptr, enc);
    // parse
    parser4<<<PCLUSTER, PR_THREADS, parsSmem>>>(missing, Wa, ba, Wt, bt, out);
}

// round 11
// speedup vs baseline: 1.0882x; 1.0328x over previous
#include <cuda_runtime.h>
#include <stdint.h>
#include <math.h>

#define NSEQ 256
#define TLEN 32
#define MROWS 8192      // NSEQ*TLEN
#define ENCD 200

// scratch (static device allocations are allowed)
__device__ float g_P  [MROWS * 800];
__device__ float g_Ya [MROWS * ENCD];
__device__ float g_Yb [MROWS * ENCD];
__device__ float g_enc[NSEQ * ENCD];
__device__ float g_stk[NSEQ * ENCD];

__device__ __forceinline__ float sigf(float x) { return 1.0f / (1.0f + expf(-x)); }
// accurate tanh via expf (robust even under fast-math)
__device__ __forceinline__ float tanh_acc(float x) {
    float e = expf(-2.0f * fabsf(x));
    float r = (1.0f - e) / (1.0f + e);
    return x >= 0.0f ? r : -r;
}
__device__ __forceinline__ float4 ldcg4(const float* p) {
    float4 v;
    asm volatile("ld.global.cg.v4.f32 {%0,%1,%2,%3}, [%4];"
                 : "=f"(v.x), "=f"(v.y), "=f"(v.z), "=f"(v.w) : "l"(p));
    return v;
}
__device__ __forceinline__ void stcg(float* p, float v) {
    asm volatile("st.global.cg.f32 [%0], %1;" :: "l"(p), "f"(v));
}
__device__ __forceinline__ unsigned int smem_u32(const void* p) {
    unsigned int a;
    asm("{ .reg .u64 t; cvta.to.shared.u64 t, %1; cvt.u32.u64 %0, t; }"
        : "=r"(a) : "l"(p));
    return a;
}
__device__ __forceinline__ unsigned int ctarank() {
    unsigned int r; asm("mov.u32 %0, %%cluster_ctarank;" : "=r"(r)); return r;
}
__device__ __forceinline__ void st_remote_f32(unsigned int laddr, unsigned int rk, float v) {
    asm volatile(
        "{ .reg .b32 ra; mapa.shared::cluster.u32 ra, %0, %1; "
        "st.shared::cluster.f32 [ra], %2; }"
        :: "r"(laddr), "r"(rk), "f"(v) : "memory");
}
__device__ __forceinline__ void mbar_init(unsigned int addr, unsigned int count) {
    asm volatile("mbarrier.init.shared.b64 [%0], %1;" :: "r"(addr), "r"(count) : "memory");
}
// remote (or self) arrive, release.cluster semantics (default)
__device__ __forceinline__ void mbar_arrive_rank(unsigned int laddr, unsigned int rk) {
    asm volatile(
        "{ .reg .b32 ra; mapa.shared::cluster.u32 ra, %0, %1; "
        "mbarrier.arrive.shared::cluster.b64 _, [ra]; }"
        :: "r"(laddr), "r"(rk) : "memory");
}
// CTA-scope acquire wait (measured best in round 9)
__device__ __forceinline__ void mbar_wait_cta(unsigned int addr, unsigned int parity) {
    asm volatile(
        "{\n\t.reg .pred P1;\n\t"
        "WL%=:\n\t"
        "mbarrier.try_wait.parity.acquire.cta.shared::cta.b64 P1, [%0], %1, 0x989680;\n\t"
        "@P1 bra.uni WD%=;\n\t"
        "bra.uni WL%=;\n\t"
        "WD%=:\n\t}"
        :: "r"(addr), "r"(parity) : "memory");
}

// ---------------------------------------------------------------------------
// P[m][800] = A[row(m)][0:K] @ W[n][0:K]^T + bias[n]
// BM=128, BN=80, BK=20, 256 threads, 8x5 micro-tile
// ---------------------------------------------------------------------------
__global__ __launch_bounds__(256) void proj_gemm(
    const float* __restrict__ Asrc, const int* __restrict__ tok,
    const float* __restrict__ W, const float* __restrict__ bias,
    float* __restrict__ P, int K)
{
    __shared__ float As[20][132];   // k-major, 128 rows + 4 pad
    __shared__ float Ws[20][80];
    __shared__ long long roff[128];

    const int tid = threadIdx.x;
    const int M0 = blockIdx.x * 128;
    const int N0 = blockIdx.y * 80;

    if (tid < 128) {
        long long o = tok ? (long long)__ldg(&tok[M0 + tid]) * (long long)K
                          : (long long)(M0 + tid) * (long long)K;
        roff[tid] = o;
    }
    const int m0 = (tid >> 4) * 8;
    const int n0 = (tid & 15) * 5;

    float acc[8][5];
#pragma unroll
    for (int i = 0; i < 8; i++)
#pragma unroll
        for (int j = 0; j < 5; j++) acc[i][j] = 0.0f;
    __syncthreads();

    for (int kt = 0; kt < K; kt += 20) {
#pragma unroll
        for (int half = 0; half < 2; half++) {
            int i0 = (tid + half * 256) * 5;
            int mm = i0 / 20, kk = i0 % 20;
            const float* ap = Asrc + roff[mm] + kt + kk;
#pragma unroll
            for (int q = 0; q < 5; q++) As[kk + q][mm] = ap[q];
        }
        for (int i = tid; i < 1600; i += 256) {
            int nn = i / 20, kk = i % 20;
            Ws[kk][nn] = __ldg(&W[(size_t)(N0 + nn) * K + kt + kk]);
        }
        __syncthreads();
#pragma unroll
        for (int kk = 0; kk < 20; kk++) {
            float4 a4lo = *(const float4*)&As[kk][m0];
            float4 a4hi = *(const float4*)&As[kk][m0 + 4];
            float a[8] = {a4lo.x, a4lo.y, a4lo.z, a4lo.w,
                          a4hi.x, a4hi.y, a4hi.z, a4hi.w};
            float b[5];
#pragma unroll
            for (int j = 0; j < 5; j++) b[j] = Ws[kk][n0 + j];
#pragma unroll
            for (int i = 0; i < 8; i++)
#pragma unroll
                for (int j = 0; j < 5; j++) acc[i][j] += a[i] * b[j];
        }
        __syncthreads();
    }
#pragma unroll
    for (int i = 0; i < 8; i++) {
        size_t row = (size_t)(M0 + m0 + i) * 800 + N0 + n0;
#pragma unroll
        for (int j = 0; j < 5; j++)
            P[row + j] = acc[i][j] + __ldg(&bias[N0 + n0 + j]);
    }
}

// ---------------------------------------------------------------------------
// LSTM recurrence (400 threads, pipelined P loads, single accumulators —
// best measured variant). If encOut != null, fuse mean-pool, skip Y.
// ---------------------------------------------------------------------------
__global__ __launch_bounds__(400, 1) void lstm_rec(
    const float* __restrict__ P, const float* __restrict__ Whh2,
    const int* __restrict__ lengths, float* __restrict__ Y,
    float* __restrict__ encOut)
{
    extern __shared__ float sm[];
    float* sW = sm;
    float* sH = sm + 40000;
    float* sC = sH + 400;
    float* sG = sC + 400;

    const int tid = threadIdx.x;
    const int dir = blockIdx.y;
    const int sq0 = blockIdx.x * 4;

    const float* Wd = Whh2 + dir * 40000;
    for (int i = tid; i < 40000; i += 400) sW[i] = Wd[i];
    for (int i = tid; i < 800; i += 400) sm[40000 + i] = 0.0f;

    const int sPW = tid / 100;
    const int jPW = tid % 100;
    const int myLen = __ldg(&lengths[sq0 + sPW]);
    __syncthreads();

    const float4* sW4 = (const float4*)(sW + tid * 100);
    const float4* sH4 = (const float4*)sH;

    float p0, p1, p2, p3;
    {
        int t = dir ? (TLEN - 1) : 0;
        size_t base = ((size_t)sq0 * TLEN + t) * 800 + dir * 400 + tid;
        p0 = __ldg(&P[base]);
        p1 = __ldg(&P[base + 1 * TLEN * 800]);
        p2 = __ldg(&P[base + 2 * TLEN * 800]);
        p3 = __ldg(&P[base + 3 * TLEN * 800]);
    }
    float hsum = 0.0f;

    for (int st = 0; st < TLEN; st++) {
        int t = dir ? (TLEN - 1 - st) : st;
        float acc0 = p0, acc1 = p1, acc2 = p2, acc3 = p3;
        if (st + 1 < TLEN) {
            int tn = dir ? (TLEN - 2 - st) : (st + 1);
            size_t base = ((size_t)sq0 * TLEN + tn) * 800 + dir * 400 + tid;
            p0 = __ldg(&P[base]);
            p1 = __ldg(&P[base + 1 * TLEN * 800]);
            p2 = __ldg(&P[base + 2 * TLEN * 800]);
            p3 = __ldg(&P[base + 3 * TLEN * 800]);
        }
#pragma unroll
        for (int kq = 0; kq < 25; kq++) {
            float4 w = sW4[kq];
            float4 h0 = sH4[kq], h1 = sH4[25 + kq], h2 = sH4[50 + kq], h3 = sH4[75 + kq];
            acc0 += w.x * h0.x + w.y * h0.y + w.z * h0.z + w.w * h0.w;
            acc1 += w.x * h1.x + w.y * h1.y + w.z * h1.z + w.w * h1.w;
            acc2 += w.x * h2.x + w.y * h2.y + w.z * h2.z + w.w * h2.w;
            acc3 += w.x * h3.x + w.y * h3.y + w.z * h3.z + w.w * h3.w;
        }
        sG[tid] = acc0; sG[400 + tid] = acc1; sG[800 + tid] = acc2; sG[1200 + tid] = acc3;
        __syncthreads();
        {
            float gi = sG[sPW * 400 + jPW];
            float gf = sG[sPW * 400 + 100 + jPW];
            float gg = sG[sPW * 400 + 200 + jPW];
            float go = sG[sPW * 400 + 300 + jPW];
            float c  = sC[sPW * 100 + jPW];
            float cn = sigf(gf) * c + sigf(gi) * tanh_acc(gg);
            float hn = sigf(go) * tanh_acc(cn);
            float outv = 0.0f;
            if (t < myLen) {
                sC[sPW * 100 + jPW] = cn;
                sH[sPW * 100 + jPW] = hn;
                outv = hn;
            }
            if (encOut) hsum += outv;
            else Y[((size_t)(sq0 + sPW) * TLEN + t) * ENCD + dir * 100 + jPW] = outv;
        }
        __syncthreads();
    }
    if (encOut)
        encOut[(sq0 + sPW) * ENCD + dir * 100 + jPW] = hsum / (float)myLen;
}

// ---------------------------------------------------------------------------
// Parser: 8-CTA cluster. CTA rank owns 13 (rank<4) or 12 units: 65/60 Wt
// rows (~52 KB) smem-resident -> per-CTA GEMV crossbar halved vs 4-CTA.
// Per step: ONE full __syncthreads; tail (decision+commit+8 arrives) is
// warp 0 only with __syncwarp; other warps fall straight into the wait.
// ---------------------------------------------------------------------------
#define PRS_WT    0
#define PRS_WA    13000
#define PRS_BT    14200
#define PRS_BUF   14272
#define PRS_G     15472
#define PRS_MISS  15540
#define PRS_SC    15740
#define PRS_MBAR  15742
#define PRS_TOTAL 15744
#define PR_THREADS 224
#define PCLUSTER 8

__global__ __cluster_dims__(PCLUSTER, 1, 1) __launch_bounds__(PR_THREADS, 1) void parser8(
    const float* __restrict__ missing, const float* __restrict__ Wa,
    const float* __restrict__ ba, const float* __restrict__ Wt,
    const float* __restrict__ bt, float* __restrict__ out)
{
    extern __shared__ float sm[];
    float* sWt   = sm + PRS_WT;    // up to 65 rows x 200
    float* sWa   = sm + PRS_WA;    // 1200
    float* sBt   = sm + PRS_BT;    // up to 65
    float* sBuf  = sm + PRS_BUF;   // 6 x 200
    float* sG    = sm + PRS_G;     // up to 65
    float* sMiss = sm + PRS_MISS;  // 200
    float* sSc   = sm + PRS_SC;    // 2
    const int tid = threadIdx.x;
    const unsigned int rank = ctarank();
    const int JC  = ((int)rank < 4) ? 13 : 12;          // units owned
    const int jlo = (int)rank * 12 + (((int)rank < 4) ? (int)rank : 4);
    const int NR  = 5 * JC;                              // gate rows owned
    const unsigned int mbarA = smem_u32(sm + PRS_MBAR);
    const unsigned int sBufA = smem_u32(sBuf);

    // own Wt rows: local row r: gate g=r/JC, unit u=r%JC -> global g*100+jlo+u
    for (int i = tid; i < NR * 200; i += PR_THREADS) {
        int r = i / 200, k = i - r * 200;
        int grow = (r / JC) * 100 + jlo + (r % JC);
        sWt[i] = __ldg(&Wt[grow * 200 + k]);
    }
    for (int i = tid; i < 1200; i += PR_THREADS) sWa[i] = __ldg(&Wa[i]);
    if (tid < NR) {
        int grow = (tid / JC) * 100 + jlo + (tid % JC);
        sBt[tid] = __ldg(&bt[grow]);
    }
    if (tid < 200) {
        float mv = __ldg(&missing[tid]);
        sMiss[tid] = mv;
        sBuf[0 * 200 + tid] = mv;                    // i1 = missing
        sBuf[1 * 200 + tid] = mv;                    // i0 = missing
        sBuf[2 * 200 + tid] = __ldg(&g_enc[tid]);    // ib = enc[0]
    }
    const float ba0 = __ldg(&ba[0]), ba1 = __ldg(&ba[1]);
    if (tid == 0) mbar_init(mbarA, PCLUSTER);
    __syncthreads();
    asm volatile("barrier.cluster.arrive.aligned;" ::: "memory");
    asm volatile("barrier.cluster.wait.aligned;"   ::: "memory");

    int i1 = 0, i0 = 1, ib = 2, ipre = 3, ibn = 4, isp = 5;
    int sp = 0, bp = 0;
    const int warp = tid >> 5;

    for (int step = 0; step < 2 * NSEQ - 1; step++) {
        // ==== PHASE A: all independent work in parallel ====
        // warps 0-4: speculative gate GEMV over own NR rows (2 threads/row)
        if (tid < 2 * NR) {
            int r = tid >> 1, ph = tid & 1;
            const float4* wp4 = (const float4*)(sWt + r * 200 + ph * 100);
            const float4* xp  = (const float4*)(sBuf + (ph ? i0 : i1) * 200);
            float acc = 0.0f;
#pragma unroll
            for (int q = 0; q < 25; q++) {
                float4 w = wp4[q], x = xp[q];
                acc += w.x * x.x + w.y * x.y + w.z * x.z + w.w * x.w;
            }
            unsigned msk = __activemask();
            acc += __shfl_xor_sync(msk, acc, 1);
            if (!ph) sG[r] = acc + sBt[r];
        }
        // warp 5: score GEMV (replicated in every CTA)
        if (warp == 5) {
            int lane = tid - 160;
            const float* w0 = sWa;
            const float* w1 = sWa + 600;
            const float* f1p = sBuf + i1 * 200;
            const float* f0p = sBuf + i0 * 200;
            const float* fbp = sBuf + ib * 200;
            float a0 = 0.0f, a1 = 0.0f;
#pragma unroll
            for (int k = 0; k < 7; k++) {
                int kk = lane + 32 * k;
                if (kk < 200) { float f = f1p[kk]; a0 += w0[kk] * f;       a1 += w1[kk] * f; }
            }
#pragma unroll
            for (int k = 0; k < 7; k++) {
                int kk = lane + 32 * k;
                if (kk < 200) { float f = f0p[kk]; a0 += w0[200 + kk] * f; a1 += w1[200 + kk] * f; }
            }
#pragma unroll
            for (int k = 0; k < 7; k++) {
                int kk = lane + 32 * k;
                if (kk < 200) { float f = fbp[kk]; a0 += w0[400 + kk] * f; a1 += w1[400 + kk] * f; }
            }
#pragma unroll
            for (int o = 16; o > 0; o >>= 1) {
                a0 += __shfl_down_sync(0xffffffffu, a0, o);
                a1 += __shfl_down_sync(0xffffffffu, a1, o);
            }
            if (lane == 0) { sSc[0] = a0 + ba0; sSc[1] = a1 + ba1; }
        }
        // warp 6: prefetch stack[sp-3] -> ipre, enc[bp+1] -> ibn
        if (warp == 6) {
            int lane = tid - 192;
            float4* dpre = (float4*)(sBuf + ipre * 200);
            float4* dbn  = (float4*)(sBuf + ibn  * 200);
            const float4* mi4 = (const float4*)sMiss;
            for (int q = lane; q < 50; q += 32)
                dpre[q] = (sp >= 3) ? ldcg4(&g_stk[(sp - 3) * ENCD + 4 * q]) : mi4[q];
            int nbp = bp + 1;
            for (int q = lane; q < 50; q += 32)
                dbn[q] = (nbp < NSEQ) ? __ldg(((const float4*)(g_enc + nbp * ENCD)) + q)
                                      : mi4[q];
        }
        __syncthreads();

        // ==== TAIL (warp 0 only): decision + commit + arrives ====
        if (warp == 0) {
            int lane = tid;
            float m0 = (bp < NSEQ) ? sSc[0] : -1e30f;
            float m1 = (sp >= 2)   ? sSc[1] : -1e30f;
            bool is_shift = (m0 >= m1);
            if (is_shift) {
                // push b: CTA writes its 25-float slice [rank*25, rank*25+25)
                if (lane < 25)
                    stcg(&g_stk[sp * ENCD + (int)rank * 25 + lane],
                         sBuf[ib * 200 + (int)rank * 25 + lane]);
            } else {
                if (lane < JC) {
                    int u = lane;
                    int j = jlo + u;
                    float gi = sG[u],          gf1 = sG[JC + u], gf2 = sG[2 * JC + u];
                    float go = sG[3 * JC + u], gu  = sG[4 * JC + u];
                    float c1 = sBuf[i1 * 200 + 100 + j];
                    float c2 = sBuf[i0 * 200 + 100 + j];
                    float c = sigf(gf1) * c1 + sigf(gf2) * c2 + sigf(gi) * tanh_acc(gu);
                    float h = sigf(go) * tanh_acc(c);
                    sBuf[isp * 200 + j]       = h;
                    sBuf[isp * 200 + 100 + j] = c;
                    unsigned int ah = sBufA + (unsigned int)(isp * 200 + j) * 4u;
                    unsigned int ac = sBufA + (unsigned int)(isp * 200 + 100 + j) * 4u;
#pragma unroll
                    for (unsigned int rk = 0; rk < PCLUSTER; rk++) {
                        if (rk != rank) { st_remote_f32(ah, rk, h); st_remote_f32(ac, rk, c); }
                    }
                    stcg(&g_stk[(sp - 2) * ENCD + j], h);
                    stcg(&g_stk[(sp - 2) * ENCD + 100 + j], c);
                }
            }
            __syncwarp(0xffffffffu);
            if (lane < PCLUSTER) mbar_arrive_rank(mbarA, (unsigned int)lane);
        }
        mbar_wait_cta(mbarA, (unsigned int)(step & 1));

        // ---- rotate ring indices (all threads, uniform across CTAs) ----
        {
            float m0 = (bp < NSEQ) ? sSc[0] : -1e30f;
            float m1 = (sp >= 2)   ? sSc[1] : -1e30f;
            bool is_shift = (m0 >= m1);
            if (is_shift) {
                int t = i1; i1 = i0; i0 = ib; ib = ibn; ibn = t;
                sp += 1; bp += 1;
            } else {
                int n1 = ipre, n0 = isp;
                ipre = i1; isp = i0;
                i1 = n1; i0 = n0;
                sp -= 1;
            }
        }
    }

    if (rank == 0 && tid < 50) {
        float4 v = ldcg4(&g_stk[4 * tid]);
        ((float4*)out)[tid] = v;
    }
}

// ---------------------------------------------------------------------------
extern "C" void kernel_launch(void* const* d_in, const int* in_sizes, int n_in,
                              void* d_out, int out_size)
{
    const int*   tokens  = (const int*)d_in[0];
    const int*   lengths = (const int*)d_in[1];
    const float* emb     = (const float*)d_in[2];
    const float* Wih0    = (const float*)d_in[3];
    const float* Whh0    = (const float*)d_in[4];
    const float* b0      = (const float*)d_in[5];
    const float* Wih12   = (const float*)d_in[6];
    const float* Whh12   = (const float*)d_in[7];
    const float* b12     = (const float*)d_in[8];
    const float* missing = (const float*)d_in[9];
    const float* Wa      = (const float*)d_in[10];
    const float* ba      = (const float*)d_in[11];
    const float* Wt      = (const float*)d_in[12];
    const float* bt      = (const float*)d_in[13];
    float* out = (float*)d_out;

    float *P, *Ya, *Yb, *enc;
    cudaGetSymbolAddress((void**)&P,  g_P);
    cudaGetSymbolAddress((void**)&Ya, g_Ya);
    cudaGetSymbolAddress((void**)&Yb, g_Yb);
    cudaGetSymbolAddress((void**)&enc, g_enc);

    const int lstmSmem = (40000 + 400 + 400 + 1600) * 4;   // 169600
    const int parsSmem = PRS_TOTAL * 4;                    // 62976
    cudaFuncSetAttribute(lstm_rec, cudaFuncAttributeMaxDynamicSharedMemorySize, lstmSmem);
    cudaFuncSetAttribute(parser8, cudaFuncAttributeMaxDynamicSharedMemorySize, parsSmem);

    dim3 gg(64, 10), rg(64, 2);

    // layer 0
    proj_gemm<<<gg, 256>>>(emb, tokens, Wih0, b0, P, 300);
    lstm_rec<<<rg, 400, lstmSmem>>>(P, Whh0, lengths, Ya, nullptr);
    // layer 1
    proj_gemm<<<gg, 256>>>(Ya, nullptr, Wih12, b12, P, 200);
    lstm_rec<<<rg, 400, lstmSmem>>>(P, Whh12, lengths, Yb, nullptr);
    // layer 2 (+ fused meanpool -> enc)
    proj_gemm<<<gg, 256>>>(Yb, nullptr, Wih12 + 160000, b12 + 800, P, 200);
    lstm_rec<<<rg, 400, lstmSmem>>>(P, Whh12 + 80000, lengths, nullptr, enc);
    // parse
    parser8<<<PCLUSTER, PR_THREADS, parsSmem>>>(missing, Wa, ba, Wt, bt, out);
}

// round 12
// speedup vs baseline: 1.1538x; 1.0603x over previous
#include <cuda_runtime.h>
#include <stdint.h>
#include <math.h>

#define NSEQ 256
#define TLEN 32
#define MROWS 8192      // NSEQ*TLEN
#define ENCD 200

// scratch (static device allocations are allowed)
__device__ float g_P  [MROWS * 800];
__device__ float g_Ya [MROWS * ENCD];
__device__ float g_Yb [MROWS * ENCD];
__device__ float g_enc[NSEQ * ENCD];
__device__ float g_stk[NSEQ * ENCD];

__device__ __forceinline__ float sigf(float x) { return 1.0f / (1.0f + expf(-x)); }
// accurate tanh via expf (robust even under fast-math)
__device__ __forceinline__ float tanh_acc(float x) {
    float e = expf(-2.0f * fabsf(x));
    float r = (1.0f - e) / (1.0f + e);
    return x >= 0.0f ? r : -r;
}
__device__ __forceinline__ float4 ldcg4(const float* p) {
    float4 v;
    asm volatile("ld.global.cg.v4.f32 {%0,%1,%2,%3}, [%4];"
                 : "=f"(v.x), "=f"(v.y), "=f"(v.z), "=f"(v.w) : "l"(p));
    return v;
}
__device__ __forceinline__ void stcg4(float* p, float4 v) {
    asm volatile("st.global.cg.v4.f32 [%0], {%1,%2,%3,%4};"
                 :: "l"(p), "f"(v.x), "f"(v.y), "f"(v.z), "f"(v.w));
}
__device__ __forceinline__ unsigned int smem_u32(const void* p) {
    unsigned int a;
    asm("{ .reg .u64 t; cvta.to.shared.u64 t, %1; cvt.u32.u64 %0, t; }"
        : "=r"(a) : "l"(p));
    return a;
}
__device__ __forceinline__ unsigned int ctarank() {
    unsigned int r; asm("mov.u32 %0, %%cluster_ctarank;" : "=r"(r)); return r;
}
__device__ __forceinline__ void st_remote_f32(unsigned int laddr, unsigned int rk, float v) {
    asm volatile(
        "{ .reg .b32 ra; mapa.shared::cluster.u32 ra, %0, %1; "
        "st.shared::cluster.f32 [ra], %2; }"
        :: "r"(laddr), "r"(rk), "f"(v) : "memory");
}
__device__ __forceinline__ void mbar_init(unsigned int addr, unsigned int count) {
    asm volatile("mbarrier.init.shared.b64 [%0], %1;" :: "r"(addr), "r"(count) : "memory");
}
// remote (or self) arrive, release.cluster semantics (default)
__device__ __forceinline__ void mbar_arrive_rank(unsigned int laddr, unsigned int rk) {
    asm volatile(
        "{ .reg .b32 ra; mapa.shared::cluster.u32 ra, %0, %1; "
        "mbarrier.arrive.shared::cluster.b64 _, [ra]; }"
        :: "r"(laddr), "r"(rk) : "memory");
}
// CTA-scope acquire wait (measured best)
__device__ __forceinline__ void mbar_wait_cta(unsigned int addr, unsigned int parity) {
    asm volatile(
        "{\n\t.reg .pred P1;\n\t"
        "WL%=:\n\t"
        "mbarrier.try_wait.parity.acquire.cta.shared::cta.b64 P1, [%0], %1, 0x989680;\n\t"
        "@P1 bra.uni WD%=;\n\t"
        "bra.uni WL%=;\n\t"
        "WD%=:\n\t}"
        :: "r"(addr), "r"(parity) : "memory");
}

// ---------------------------------------------------------------------------
// P[m][800] = A[row(m)][0:K] @ W[n][0:K]^T + bias[n]
// BM=128, BN=80, BK=20, 256 threads, 8x5 micro-tile
// ---------------------------------------------------------------------------
__global__ __launch_bounds__(256) void proj_gemm(
    const float* __restrict__ Asrc, const int* __restrict__ tok,
    const float* __restrict__ W, const float* __restrict__ bias,
    float* __restrict__ P, int K)
{
    __shared__ float As[20][132];   // k-major, 128 rows + 4 pad
    __shared__ float Ws[20][80];
    __shared__ long long roff[128];

    const int tid = threadIdx.x;
    const int M0 = blockIdx.x * 128;
    const int N0 = blockIdx.y * 80;

    if (tid < 128) {
        long long o = tok ? (long long)__ldg(&tok[M0 + tid]) * (long long)K
                          : (long long)(M0 + tid) * (long long)K;
        roff[tid] = o;
    }
    const int m0 = (tid >> 4) * 8;
    const int n0 = (tid & 15) * 5;

    float acc[8][5];
#pragma unroll
    for (int i = 0; i < 8; i++)
#pragma unroll
        for (int j = 0; j < 5; j++) acc[i][j] = 0.0f;
    __syncthreads();

    for (int kt = 0; kt < K; kt += 20) {
#pragma unroll
        for (int half = 0; half < 2; half++) {
            int i0 = (tid + half * 256) * 5;
            int mm = i0 / 20, kk = i0 % 20;
            const float* ap = Asrc + roff[mm] + kt + kk;
#pragma unroll
            for (int q = 0; q < 5; q++) As[kk + q][mm] = ap[q];
        }
        for (int i = tid; i < 1600; i += 256) {
            int nn = i / 20, kk = i % 20;
            Ws[kk][nn] = __ldg(&W[(size_t)(N0 + nn) * K + kt + kk]);
        }
        __syncthreads();
#pragma unroll
        for (int kk = 0; kk < 20; kk++) {
            float4 a4lo = *(const float4*)&As[kk][m0];
            float4 a4hi = *(const float4*)&As[kk][m0 + 4];
            float a[8] = {a4lo.x, a4lo.y, a4lo.z, a4lo.w,
                          a4hi.x, a4hi.y, a4hi.z, a4hi.w};
            float b[5];
#pragma unroll
            for (int j = 0; j < 5; j++) b[j] = Ws[kk][n0 + j];
#pragma unroll
            for (int i = 0; i < 8; i++)
#pragma unroll
                for (int j = 0; j < 5; j++) acc[i][j] += a[i] * b[j];
        }
        __syncthreads();
    }
#pragma unroll
    for (int i = 0; i < 8; i++) {
        size_t row = (size_t)(M0 + m0 + i) * 800 + N0 + n0;
#pragma unroll
        for (int j = 0; j < 5; j++)
            P[row + j] = acc[i][j] + __ldg(&bias[N0 + n0 + j]);
    }
}

// ---------------------------------------------------------------------------
// LSTM recurrence (400 threads, pipelined P loads, single accumulators).
// If encOut != null, fuse mean-pool, skip Y.
// ---------------------------------------------------------------------------
__global__ __launch_bounds__(400, 1) void lstm_rec(
    const float* __restrict__ P, const float* __restrict__ Whh2,
    const int* __restrict__ lengths, float* __restrict__ Y,
    float* __restrict__ encOut)
{
    extern __shared__ float sm[];
    float* sW = sm;
    float* sH = sm + 40000;
    float* sC = sH + 400;
    float* sG = sC + 400;

    const int tid = threadIdx.x;
    const int dir = blockIdx.y;
    const int sq0 = blockIdx.x * 4;

    const float* Wd = Whh2 + dir * 40000;
    for (int i = tid; i < 40000; i += 400) sW[i] = Wd[i];
    for (int i = tid; i < 800; i += 400) sm[40000 + i] = 0.0f;

    const int sPW = tid / 100;
    const int jPW = tid % 100;
    const int myLen = __ldg(&lengths[sq0 + sPW]);
    __syncthreads();

    const float4* sW4 = (const float4*)(sW + tid * 100);
    const float4* sH4 = (const float4*)sH;

    float p0, p1, p2, p3;
    {
        int t = dir ? (TLEN - 1) : 0;
        size_t base = ((size_t)sq0 * TLEN + t) * 800 + dir * 400 + tid;
        p0 = __ldg(&P[base]);
        p1 = __ldg(&P[base + 1 * TLEN * 800]);
        p2 = __ldg(&P[base + 2 * TLEN * 800]);
        p3 = __ldg(&P[base + 3 * TLEN * 800]);
    }
    float hsum = 0.0f;

    for (int st = 0; st < TLEN; st++) {
        int t = dir ? (TLEN - 1 - st) : st;
        float acc0 = p0, acc1 = p1, acc2 = p2, acc3 = p3;
        if (st + 1 < TLEN) {
            int tn = dir ? (TLEN - 2 - st) : (st + 1);
            size_t base = ((size_t)sq0 * TLEN + tn) * 800 + dir * 400 + tid;
            p0 = __ldg(&P[base]);
            p1 = __ldg(&P[base + 1 * TLEN * 800]);
            p2 = __ldg(&P[base + 2 * TLEN * 800]);
            p3 = __ldg(&P[base + 3 * TLEN * 800]);
        }
#pragma unroll
        for (int kq = 0; kq < 25; kq++) {
            float4 w = sW4[kq];
            float4 h0 = sH4[kq], h1 = sH4[25 + kq], h2 = sH4[50 + kq], h3 = sH4[75 + kq];
            acc0 += w.x * h0.x + w.y * h0.y + w.z * h0.z + w.w * h0.w;
            acc1 += w.x * h1.x + w.y * h1.y + w.z * h1.z + w.w * h1.w;
            acc2 += w.x * h2.x + w.y * h2.y + w.z * h2.z + w.w * h2.w;
            acc3 += w.x * h3.x + w.y * h3.y + w.z * h3.z + w.w * h3.w;
        }
        sG[tid] = acc0; sG[400 + tid] = acc1; sG[800 + tid] = acc2; sG[1200 + tid] = acc3;
        __syncthreads();
        {
            float gi = sG[sPW * 400 + jPW];
            float gf = sG[sPW * 400 + 100 + jPW];
            float gg = sG[sPW * 400 + 200 + jPW];
            float go = sG[sPW * 400 + 300 + jPW];
            float c  = sC[sPW * 100 + jPW];
            float cn = sigf(gf) * c + sigf(gi) * tanh_acc(gg);
            float hn = sigf(go) * tanh_acc(cn);
            float outv = 0.0f;
            if (t < myLen) {
                sC[sPW * 100 + jPW] = cn;
                sH[sPW * 100 + jPW] = hn;
                outv = hn;
            }
            if (encOut) hsum += outv;
            else Y[((size_t)(sq0 + sPW) * TLEN + t) * ENCD + dir * 100 + jPW] = outv;
        }
        __syncthreads();
    }
    if (encOut)
        encOut[(sq0 + sPW) * ENCD + dir * 100 + jPW] = hsum / (float)myLen;
}

// ---------------------------------------------------------------------------
// Parser: 8-CTA cluster, barrier ONLY on reduce steps.
// g_stk is CTA-redundant: every CTA writes full 200-float rows (shift: warp 0
// pushes b; reduce: merged written back by warp 6 in the NEXT step's phase A).
// All g_stk prefetch reads are own-CTA writes -> shift steps need no cluster
// sync at all. Reduce keeps DSMEM exchange + mbarrier (parity = reduce count).
// ---------------------------------------------------------------------------
#define PRS_WT    0
#define PRS_WA    13000
#define PRS_BT    14200
#define PRS_BUF   14272
#define PRS_G     15472
#define PRS_MISS  15540
#define PRS_SC    15740
#define PRS_MBAR  15742
#define PRS_TOTAL 15744
#define PR_THREADS 224
#define PCLUSTER 8

__global__ __cluster_dims__(PCLUSTER, 1, 1) __launch_bounds__(PR_THREADS, 1) void parser8(
    const float* __restrict__ missing, const float* __restrict__ Wa,
    const float* __restrict__ ba, const float* __restrict__ Wt,
    const float* __restrict__ bt, float* __restrict__ out)
{
    extern __shared__ float sm[];
    float* sWt   = sm + PRS_WT;    // up to 65 rows x 200
    float* sWa   = sm + PRS_WA;    // 1200
    float* sBt   = sm + PRS_BT;    // up to 65
    float* sBuf  = sm + PRS_BUF;   // 6 x 200
    float* sG    = sm + PRS_G;     // up to 65
    float* sMiss = sm + PRS_MISS;  // 200
    float* sSc   = sm + PRS_SC;    // 2
    const int tid = threadIdx.x;
    const unsigned int rank = ctarank();
    const int JC  = ((int)rank < 4) ? 13 : 12;          // units owned
    const int jlo = (int)rank * 12 + (((int)rank < 4) ? (int)rank : 4);
    const int NR  = 5 * JC;                              // gate rows owned
    const unsigned int mbarA = smem_u32(sm + PRS_MBAR);
    const unsigned int sBufA = smem_u32(sBuf);

    for (int i = tid; i < NR * 200; i += PR_THREADS) {
        int r = i / 200, k = i - r * 200;
        int grow = (r / JC) * 100 + jlo + (r % JC);
        sWt[i] = __ldg(&Wt[grow * 200 + k]);
    }
    for (int i = tid; i < 1200; i += PR_THREADS) sWa[i] = __ldg(&Wa[i]);
    if (tid < NR) {
        int grow = (tid / JC) * 100 + jlo + (tid % JC);
        sBt[tid] = __ldg(&bt[grow]);
    }
    if (tid < 200) {
        float mv = __ldg(&missing[tid]);
        sMiss[tid] = mv;
        sBuf[0 * 200 + tid] = mv;                    // i1 = missing
        sBuf[1 * 200 + tid] = mv;                    // i0 = missing
        sBuf[2 * 200 + tid] = __ldg(&g_enc[tid]);    // ib = enc[0]
    }
    const float ba0 = __ldg(&ba[0]), ba1 = __ldg(&ba[1]);
    if (tid == 0) mbar_init(mbarA, PCLUSTER);
    __syncthreads();
    asm volatile("barrier.cluster.arrive.aligned;" ::: "memory");
    asm volatile("barrier.cluster.wait.aligned;"   ::: "memory");

    int i1 = 0, i0 = 1, ib = 2, ipre = 3, ibn = 4, isp = 5;
    int sp = 0, bp = 0;
    int rp = 0;                // reduce parity
    int pendWp = -1;           // pending merged -> g_stk writeback row
    const int warp = tid >> 5;

    for (int step = 0; step < 2 * NSEQ - 1; step++) {
        // ==== PHASE A: all independent work in parallel ====
        // warps 0-4: speculative gate GEMV over own NR rows (2 threads/row)
        if (tid < 2 * NR) {
            int r = tid >> 1, ph = tid & 1;
            const float4* wp4 = (const float4*)(sWt + r * 200 + ph * 100);
            const float4* xp  = (const float4*)(sBuf + (ph ? i0 : i1) * 200);
            float acc = 0.0f;
#pragma unroll
            for (int q = 0; q < 25; q++) {
                float4 w = wp4[q], x = xp[q];
                acc += w.x * x.x + w.y * x.y + w.z * x.z + w.w * x.w;
            }
            unsigned msk = __activemask();
            acc += __shfl_xor_sync(msk, acc, 1);
            if (!ph) sG[r] = acc + sBt[r];
        }
        // warp 5: score GEMV (replicated in every CTA)
        if (warp == 5) {
            int lane = tid - 160;
            const float* w0 = sWa;
            const float* w1 = sWa + 600;
            const float* f1p = sBuf + i1 * 200;
            const float* f0p = sBuf + i0 * 200;
            const float* fbp = sBuf + ib * 200;
            float a0 = 0.0f, a1 = 0.0f;
#pragma unroll
            for (int k = 0; k < 7; k++) {
                int kk = lane + 32 * k;
                if (kk < 200) { float f = f1p[kk]; a0 += w0[kk] * f;       a1 += w1[kk] * f; }
            }
#pragma unroll
            for (int k = 0; k < 7; k++) {
                int kk = lane + 32 * k;
                if (kk < 200) { float f = f0p[kk]; a0 += w0[200 + kk] * f; a1 += w1[200 + kk] * f; }
            }
#pragma unroll
            for (int k = 0; k < 7; k++) {
                int kk = lane + 32 * k;
                if (kk < 200) { float f = fbp[kk]; a0 += w0[400 + kk] * f; a1 += w1[400 + kk] * f; }
            }
#pragma unroll
            for (int o = 16; o > 0; o >>= 1) {
                a0 += __shfl_down_sync(0xffffffffu, a0, o);
                a1 += __shfl_down_sync(0xffffffffu, a1, o);
            }
            if (lane == 0) { sSc[0] = a0 + ba0; sSc[1] = a1 + ba1; }
        }
        // warp 6: pending merged writeback + prefetch stack[sp-3], enc[bp+1]
        if (warp == 6) {
            int lane = tid - 192;
            if (pendWp >= 0) {   // write previous step's merged (slot i1 after
                                 // reduce rotation? no: merged is at i0) fully
                const float4* src = (const float4*)(sBuf + i0 * 200);
                for (int q = lane; q < 50; q += 32)
                    stcg4(&g_stk[pendWp * ENCD + 4 * q], src[q]);
            }
            float4* dpre = (float4*)(sBuf + ipre * 200);
            float4* dbn  = (float4*)(sBuf + ibn  * 200);
            const float4* mi4 = (const float4*)sMiss;
            for (int q = lane; q < 50; q += 32)
                dpre[q] = (sp >= 3) ? ldcg4(&g_stk[(sp - 3) * ENCD + 4 * q]) : mi4[q];
            int nbp = bp + 1;
            for (int q = lane; q < 50; q += 32)
                dbn[q] = (nbp < NSEQ) ? __ldg(((const float4*)(g_enc + nbp * ENCD)) + q)
                                      : mi4[q];
        }
        pendWp = -1;
        __syncthreads();

        // ==== PHASE B ====
        float m0 = (bp < NSEQ) ? sSc[0] : -1e30f;
        float m1 = (sp >= 2)   ? sSc[1] : -1e30f;
        bool is_shift = (m0 >= m1);   // argmax, first-index tie-break

        if (is_shift) {
            // push FULL b vector (CTA-redundant stack) — no cluster sync
            if (warp == 0 && tid < 25) {
                const float4* src = (const float4*)(sBuf + ib * 200);
                stcg4(&g_stk[sp * ENCD + 8 * tid],     src[2 * tid]);
                stcg4(&g_stk[sp * ENCD + 8 * tid + 4], src[2 * tid + 1]);
            }
            int t = i1; i1 = i0; i0 = ib; ib = ibn; ibn = t;
            sp += 1; bp += 1;
        } else {
            if (warp == 0) {
                if (tid < JC) {
                    int u = tid;
                    int j = jlo + u;
                    float gi = sG[u],          gf1 = sG[JC + u], gf2 = sG[2 * JC + u];
                    float go = sG[3 * JC + u], gu  = sG[4 * JC + u];
                    float c1 = sBuf[i1 * 200 + 100 + j];
                    float c2 = sBuf[i0 * 200 + 100 + j];
                    float c = sigf(gf1) * c1 + sigf(gf2) * c2 + sigf(gi) * tanh_acc(gu);
                    float h = sigf(go) * tanh_acc(c);
                    sBuf[isp * 200 + j]       = h;
                    sBuf[isp * 200 + 100 + j] = c;
                    unsigned int ah = sBufA + (unsigned int)(isp * 200 + j) * 4u;
                    unsigned int ac = sBufA + (unsigned int)(isp * 200 + 100 + j) * 4u;
#pragma unroll
                    for (unsigned int rk = 0; rk < PCLUSTER; rk++) {
                        if (rk != rank) { st_remote_f32(ah, rk, h); st_remote_f32(ac, rk, c); }
                    }
                }
                __syncwarp(0xffffffffu);
                if (tid < PCLUSTER) mbar_arrive_rank(mbarA, (unsigned int)tid);
            }
            mbar_wait_cta(mbarA, (unsigned int)rp);
            rp ^= 1;
            pendWp = sp - 2;           // merged -> g_stk next step (off path)
            int n1 = ipre, n0 = isp;
            ipre = i1; isp = i0;
            i1 = n1; i0 = n0;          // merged now at i0
            sp -= 1;
        }
    }

    // final stack[0] = last merged = sBuf[i0] (h | c)
    if (rank == 0 && tid < 200) out[tid] = sBuf[i0 * 200 + tid];
}

// ---------------------------------------------------------------------------
extern "C" void kernel_launch(void* const* d_in, const int* in_sizes, int n_in,
                              void* d_out, int out_size)
{
    const int*   tokens  = (const int*)d_in[0];
    const int*   lengths = (const int*)d_in[1];
    const float* emb     = (const float*)d_in[2];
    const float* Wih0    = (const float*)d_in[3];
    const float* Whh0    = (const float*)d_in[4];
    const float* b0      = (const float*)d_in[5];
    const float* Wih12   = (const float*)d_in[6];
    const float* Whh12   = (const float*)d_in[7];
    const float* b12     = (const float*)d_in[8];
    const float* missing = (const float*)d_in[9];
    const float* Wa      = (const float*)d_in[10];
    const float* ba      = (const float*)d_in[11];
    const float* Wt      = (const float*)d_in[12];
    const float* bt      = (const float*)d_in[13];
    float* out = (float*)d_out;

    float *P, *Ya, *Yb, *enc;
    cudaGetSymbolAddress((void**)&P,  g_P);
    cudaGetSymbolAddress((void**)&Ya, g_Ya);
    cudaGetSymbolAddress((void**)&Yb, g_Yb);
    cudaGetSymbolAddress((void**)&enc, g_enc);

    const int lstmSmem = (40000 + 400 + 400 + 1600) * 4;   // 169600
    const int parsSmem = PRS_TOTAL * 4;                    // 62976
    cudaFuncSetAttribute(lstm_rec, cudaFuncAttributeMaxDynamicSharedMemorySize, lstmSmem);
    cudaFuncSetAttribute(parser8, cudaFuncAttributeMaxDynamicSharedMemorySize, parsSmem);

    dim3 gg(64, 10), rg(64, 2);

    // layer 0
    proj_gemm<<<gg, 256>>>(emb, tokens, Wih0, b0, P, 300);
    lstm_rec<<<rg, 400, lstmSmem>>>(P, Whh0, lengths, Ya, nullptr);
    // layer 1
    proj_gemm<<<gg, 256>>>(Ya, nullptr, Wih12, b12, P, 200);
    lstm_rec<<<rg, 400, lstmSmem>>>(P, Whh12, lengths, Yb, nullptr);
    // layer 2 (+ fused meanpool -> enc)
    proj_gemm<<<gg, 256>>>(Yb, nullptr, Wih12 + 160000, b12 + 800, P, 200);
    lstm_rec<<<rg, 400, lstmSmem>>>(P, Whh12 + 80000, lengths, nullptr, enc);
    // parse
    parser8<<<PCLUSTER, PR_THREADS, parsSmem>>>(missing, Wa, ba, Wt, bt, out);
}